// round 13
// baseline (speedup 1.0000x reference)
#include <cuda_runtime.h>
#include <cuda_fp16.h>
#include <cstdint>

// ---------------- problem constants ----------------
constexpr int Cdim = 768;
constexpr int Bn   = 8;
constexpr int Nn   = 1024;
constexpr int HDn  = 192;            // head dim
constexpr int Sn   = Bn * Nn;        // 8192 rows
constexpr int BHn  = Bn * 4;         // 32
constexpr int CEN  = 20;
constexpr float EPSv = 1e-5f;

// ---------------- scratch (device globals; no allocation allowed) ----------------
__device__ __half g_h     [Sn * Cdim];
__device__ __half g_qkvwr [3 * Cdim * Cdim];
__device__ __half g_projwr[Cdim * Cdim];
__device__ __half g_Qg  [BHn * Nn * HDn];
__device__ __half g_Kg  [BHn * Nn * HDn];
__device__ __half g_Vg  [BHn * Nn * HDn];
__device__ __half g_KM  [BHn * Nn * HDn];   // KM2 = K @ (2*scale*M)^T
__device__ __half g_Mh  [HDn * HDn];        // 2*scale*M (half)
__device__ float  g_kbp [3 * BHn * Nn];     // kbias partials (one per N-block)
__device__ float  g_kb  [BHn * Nn];
__device__ __half g_y   [Sn * Cdim];
__device__ float  g_x1  [Sn * Cdim];

// ---------------- helpers ----------------
__device__ __forceinline__ float warpsum32(float v) {
#pragma unroll
    for (int o = 16; o >= 1; o >>= 1) v += __shfl_xor_sync(0xffffffffu, v, o);
    return v;
}
__device__ __forceinline__ uint32_t h2u(__half2 h) {
    return *reinterpret_cast<uint32_t*>(&h);
}
__device__ __forceinline__ __half2 u2h(uint32_t u) {
    return *reinterpret_cast<__half2*>(&u);
}
__device__ __forceinline__ void mma16h(float* c,
    uint32_t a0, uint32_t a1, uint32_t a2, uint32_t a3, uint32_t b0, uint32_t b1)
{
    asm volatile("mma.sync.aligned.m16n8k16.row.col.f32.f16.f16.f32 "
        "{%0,%1,%2,%3}, {%4,%5,%6,%7}, {%8,%9}, {%0,%1,%2,%3};"
        : "+f"(c[0]), "+f"(c[1]), "+f"(c[2]), "+f"(c[3])
        : "r"(a0), "r"(a1), "r"(a2), "r"(a3), "r"(b0), "r"(b1));
}
__device__ __forceinline__ void ldsm4(uint32_t& r0, uint32_t& r1, uint32_t& r2, uint32_t& r3,
                                      uint32_t addr)
{
    asm volatile("ldmatrix.sync.aligned.m8n8.x4.shared.b16 {%0,%1,%2,%3}, [%4];"
        : "=r"(r0), "=r"(r1), "=r"(r2), "=r"(r3) : "r"(addr));
}
__device__ __forceinline__ void ldsm4t(uint32_t& r0, uint32_t& r1, uint32_t& r2, uint32_t& r3,
                                       uint32_t addr)
{
    asm volatile("ldmatrix.sync.aligned.m8n8.x4.trans.shared.b16 {%0,%1,%2,%3}, [%4];"
        : "=r"(r0), "=r"(r1), "=r"(r2), "=r"(r3) : "r"(addr));
}
__device__ __forceinline__ void cp_async16(void* smem, const void* gmem) {
    uint32_t s = (uint32_t)__cvta_generic_to_shared(smem);
    asm volatile("cp.async.cg.shared.global [%0], [%1], 16;\n" :: "r"(s), "l"(gmem));
}
__device__ __forceinline__ void cp_commit() {
    asm volatile("cp.async.commit_group;\n");
}
template<int N>
__device__ __forceinline__ void cp_wait() {
    asm volatile("cp.async.wait_group %0;\n" :: "n"(N));
}

// ---------------- LayerNorm (LN1): 2 rows per warp, half output ----------------
__global__ __launch_bounds__(256) void ln1_kernel(
    const float* __restrict__ x, const float* __restrict__ w,
    const float* __restrict__ b, __half* __restrict__ out)
{
    const int row0 = blockIdx.x * 16 + (threadIdx.x >> 5) * 2;
    const int lane = threadIdx.x & 31;
    const float4* xr0 = (const float4*)(x + (size_t)row0 * Cdim);
    const float4* xr1 = (const float4*)(x + (size_t)(row0 + 1) * Cdim);
    float4 v0[6], v1[6];
    float s0 = 0.f, s20 = 0.f, s1 = 0.f, s21 = 0.f;
#pragma unroll
    for (int i = 0; i < 6; i++) {
        v0[i] = xr0[lane + i * 32];
        v1[i] = xr1[lane + i * 32];
    }
#pragma unroll
    for (int i = 0; i < 6; i++) {
        s0  += v0[i].x + v0[i].y + v0[i].z + v0[i].w;
        s20 += v0[i].x * v0[i].x + v0[i].y * v0[i].y + v0[i].z * v0[i].z + v0[i].w * v0[i].w;
        s1  += v1[i].x + v1[i].y + v1[i].z + v1[i].w;
        s21 += v1[i].x * v1[i].x + v1[i].y * v1[i].y + v1[i].z * v1[i].z + v1[i].w * v1[i].w;
    }
    s0 = warpsum32(s0); s20 = warpsum32(s20);
    s1 = warpsum32(s1); s21 = warpsum32(s21);
    const float mu0 = s0 * (1.0f / Cdim);
    const float rs0 = rsqrtf(s20 * (1.0f / Cdim) - mu0 * mu0 + EPSv);
    const float mu1 = s1 * (1.0f / Cdim);
    const float rs1 = rsqrtf(s21 * (1.0f / Cdim) - mu1 * mu1 + EPSv);
    const float4* w4 = (const float4*)w;
    const float4* b4 = (const float4*)b;
#pragma unroll
    for (int i = 0; i < 6; i++) {
        const int idx = lane + i * 32;
        const float4 wv = w4[idx], bv = b4[idx];
        __half* o0 = out + (size_t)row0 * Cdim + 4 * idx;
        __half* o1 = out + (size_t)(row0 + 1) * Cdim + 4 * idx;
        *(__half2*)&o0[0] = __floats2half2_rn((v0[i].x - mu0) * rs0 * wv.x + bv.x,
                                              (v0[i].y - mu0) * rs0 * wv.y + bv.y);
        *(__half2*)&o0[2] = __floats2half2_rn((v0[i].z - mu0) * rs0 * wv.z + bv.z,
                                              (v0[i].w - mu0) * rs0 * wv.w + bv.w);
        *(__half2*)&o1[0] = __floats2half2_rn((v1[i].x - mu1) * rs1 * wv.x + bv.x,
                                              (v1[i].y - mu1) * rs1 * wv.y + bv.y);
        *(__half2*)&o1[2] = __floats2half2_rn((v1[i].z - mu1) * rs1 * wv.z + bv.z,
                                              (v1[i].w - mu1) * rs1 * wv.w + bv.w);
    }
}

// ---------------- f32 -> f16 copy (vectorized) ----------------
__global__ __launch_bounds__(256) void half_copy4_kernel(
    const float4* __restrict__ src, __half* __restrict__ dst, int n4)
{
    for (int i = blockIdx.x * 256 + threadIdx.x; i < n4; i += gridDim.x * 256) {
        const float4 v = src[i];
        *(__half2*)&dst[4 * i]     = __floats2half2_rn(v.x, v.y);
        *(__half2*)&dst[4 * i + 2] = __floats2half2_rn(v.z, v.w);
    }
}

// ---------------- Mh = 2*scale*M (half, same layout) ----------------
__global__ __launch_bounds__(256) void scale_m_kernel(
    const float* __restrict__ M, const float* __restrict__ scale_p,
    __half* __restrict__ Mh)
{
    const int i = blockIdx.x * 256 + threadIdx.x;
    if (i >= HDn * HDn) return;
    Mh[i] = __float2half(2.0f * scale_p[0] * M[i]);
}

// ---------------- 3-stage pipelined fp16 NT GEMM: C = A[M,K] * B[N,K]^T ----------------
// MODE 0: half store. MODE 1: qkv scatter -> Q/K/V half [BH][N][HD]. MODE 2: fp32 +bias+resid.
// MODE 3: half store + kbias partials kbp[bx*Md + row] = sum_n A[row,n]*acc[row,n].
template<int BN, int MODE>
__global__ __launch_bounds__(256) void gemm_h(
    const __half* __restrict__ A, const __half* __restrict__ B, void* __restrict__ Cv,
    __half* __restrict__ C2, __half* __restrict__ C3,
    int Md, int Nd, int Kd,
    const float* __restrict__ bias, const float* __restrict__ resid,
    float* __restrict__ kbp)
{
    constexpr int BM = 128, BK = 64;
    constexpr int WM = (BN == 128) ? 2 : 4;
    constexpr int WN = 8 / WM;
    constexpr int WTM = BM / WM, WTN = BN / WN;
    constexpr int MT = WTM / 16, NT = WTN / 8;
    constexpr int ASTG = BM * BK;
    constexpr int BSTG = BN * BK;

    extern __shared__ __align__(16) __half smh[];
    __half* As = smh;                 // 3 stages
    __half* Bs = smh + 3 * ASTG;      // 3 stages

    const int t = threadIdx.x;
    const int wid = t >> 5, lane = t & 31;
    const int wm = wid % WM, wn = wid / WM;
    const int lr4 = lane >> 2, lc4 = lane & 3;
    const int g8 = lane >> 3, l8 = lane & 7;
    const int m0 = blockIdx.y * BM, n0 = blockIdx.x * BN;

    const __half* Ab = A + (size_t)m0 * Kd;
    const __half* Bb = B + (size_t)n0 * Kd;

    auto prefetch = [&](int kt, int st) {
        const __half* Ag = Ab + kt * BK;
        const __half* Bg = Bb + kt * BK;
#pragma unroll
        for (int i = 0; i < BM / 32; i++) {
            const int ch = t + i * 256;
            const int r = ch >> 3, c = ch & 7;
            cp_async16(&As[st * ASTG + (r * 8 + (c ^ (r & 7))) * 8], Ag + (size_t)r * Kd + c * 8);
        }
#pragma unroll
        for (int i = 0; i < BN / 32; i++) {
            const int ch = t + i * 256;
            const int r = ch >> 3, c = ch & 7;
            cp_async16(&Bs[st * BSTG + (r * 8 + (c ^ (r & 7))) * 8], Bg + (size_t)r * Kd + c * 8);
        }
    };

    float acc[MT][NT][4];
#pragma unroll
    for (int i = 0; i < MT; i++)
#pragma unroll
        for (int j = 0; j < NT; j++)
#pragma unroll
            for (int q = 0; q < 4; q++) acc[i][j][q] = 0.f;

    const int nK = Kd / BK;
    prefetch(0, 0); cp_commit();
    prefetch(1, 1); cp_commit();

    for (int kt = 0; kt < nK; kt++) {
        cp_wait<1>();
        __syncthreads();
        if (kt + 2 < nK) prefetch(kt + 2, (kt + 2) % 3);
        cp_commit();

        const int st = kt % 3;
        const uint32_t Au = (uint32_t)__cvta_generic_to_shared(As + st * ASTG);
        const uint32_t Bu = (uint32_t)__cvta_generic_to_shared(Bs + st * BSTG);

#pragma unroll
        for (int k16 = 0; k16 < BK / 16; k16++) {
            uint32_t bf[NT][2];
#pragma unroll
            for (int p = 0; p < NT / 2; p++) {
                const int row = wn * WTN + p * 16 + (g8 >> 1) * 8 + l8;
                const int ch  = (2 * k16 + (g8 & 1)) ^ l8;
                ldsm4(bf[2 * p][0], bf[2 * p][1], bf[2 * p + 1][0], bf[2 * p + 1][1],
                      Bu + (row * 8 + ch) * 16);
            }
#pragma unroll
            for (int mt = 0; mt < MT; mt++) {
                const int rowA = wm * WTM + mt * 16 + (g8 & 1) * 8 + l8;
                const int chA  = (2 * k16 + (g8 >> 1)) ^ l8;
                uint32_t a0, a1, a2, a3;
                ldsm4(a0, a1, a2, a3, Au + (rowA * 8 + chA) * 16);
#pragma unroll
                for (int nt = 0; nt < NT; nt++)
                    mma16h(acc[mt][nt], a0, a1, a2, a3, bf[nt][0], bf[nt][1]);
            }
        }
    }

    float part[MT][2];
    if (MODE == 3) {
#pragma unroll
        for (int mt = 0; mt < MT; mt++) { part[mt][0] = 0.f; part[mt][1] = 0.f; }
    }

#pragma unroll
    for (int mt = 0; mt < MT; mt++) {
        const int mbase = m0 + wm * WTM + mt * 16 + lr4;
#pragma unroll
        for (int nt = 0; nt < NT; nt++) {
            const int n = n0 + wn * WTN + nt * 8 + 2 * lc4;
            if (MODE == 0 || MODE == 3) {
                __half* C = (__half*)Cv;
                *(__half2*)&C[(size_t)mbase * Nd + n] =
                    __floats2half2_rn(acc[mt][nt][0], acc[mt][nt][1]);
                *(__half2*)&C[(size_t)(mbase + 8) * Nd + n] =
                    __floats2half2_rn(acc[mt][nt][2], acc[mt][nt][3]);
                if (MODE == 3) {
                    const float2 k0 = __half22float2(*(const __half2*)&A[(size_t)mbase * Kd + n]);
                    const float2 k1 = __half22float2(*(const __half2*)&A[(size_t)(mbase + 8) * Kd + n]);
                    part[mt][0] += k0.x * acc[mt][nt][0] + k0.y * acc[mt][nt][1];
                    part[mt][1] += k1.x * acc[mt][nt][2] + k1.y * acc[mt][nt][3];
                }
            } else if (MODE == 1) {
                const int which = n / Cdim;
                const int rem = n % Cdim;
                const int h = rem / HDn, d = rem % HDn;
                __half* dst = (which == 0) ? (__half*)Cv : (which == 1) ? C2 : C3;
#pragma unroll
                for (int rr = 0; rr < 2; rr++) {
                    const int m = mbase + rr * 8;
                    const int b = m >> 10, nr = m & 1023;
                    const size_t di = ((size_t)((b << 2) + h) * Nn + nr) * HDn + d;
                    *(__half2*)&dst[di] =
                        __floats2half2_rn(acc[mt][nt][rr * 2], acc[mt][nt][rr * 2 + 1]);
                }
            } else {
                float* C = (float*)Cv;
                const float b0 = bias[n], b1 = bias[n + 1];
                const size_t i0 = (size_t)mbase * Nd + n;
                const size_t i1 = (size_t)(mbase + 8) * Nd + n;
                *(float2*)&C[i0] = make_float2(acc[mt][nt][0] + b0 + resid[i0],
                                               acc[mt][nt][1] + b1 + resid[i0 + 1]);
                *(float2*)&C[i1] = make_float2(acc[mt][nt][2] + b0 + resid[i1],
                                               acc[mt][nt][3] + b1 + resid[i1 + 1]);
            }
        }
    }

    if (MODE == 3) {
        float pr[MT][2];
#pragma unroll
        for (int mt = 0; mt < MT; mt++)
#pragma unroll
            for (int sr = 0; sr < 2; sr++) {
                float p = part[mt][sr];
                p += __shfl_xor_sync(0xffffffffu, p, 1);
                p += __shfl_xor_sync(0xffffffffu, p, 2);
                pr[mt][sr] = p;
            }
        __syncthreads();
        float* sred = (float*)smh;
        if (wn == 0 && lc4 == 0) {
#pragma unroll
            for (int mt = 0; mt < MT; mt++)
#pragma unroll
                for (int sr = 0; sr < 2; sr++)
                    sred[wm * WTM + mt * 16 + sr * 8 + lr4] = pr[mt][sr];
        }
        __syncthreads();
        if (wn == 1 && lc4 == 0) {
#pragma unroll
            for (int mt = 0; mt < MT; mt++)
#pragma unroll
                for (int sr = 0; sr < 2; sr++) {
                    const int rl = wm * WTM + mt * 16 + sr * 8 + lr4;
                    kbp[(size_t)blockIdx.x * Md + m0 + rl] = sred[rl] + pr[mt][sr];
                }
        }
    }
}

// ---------------- kb[r] = -0.5 * (kbp[0][r] + kbp[1][r] + kbp[2][r]) ----------------
__global__ __launch_bounds__(256) void kb_reduce_kernel(
    const float* __restrict__ kbp, float* __restrict__ kb)
{
    const int r = blockIdx.x * 256 + threadIdx.x;
    if (r >= BHn * Nn) return;
    kb[r] = -0.5f * (kbp[r] + kbp[BHn * Nn + r] + kbp[2 * BHn * Nn + r]);
}

// ---------------- fp16 flash attention (3-stage): S = q . KM2 + kb ----------------
constexpr int KSs = 200;        // K/V smem stride (halfs)
constexpr int KVST = 64 * KSs;  // halfs per stage
constexpr int ATT_SMEM = 3 * 2 * KVST * 2 + 3 * 64 * 4;   // 154368 B

__global__ __launch_bounds__(256, 1) void attn_tc_kernel(
    const __half* __restrict__ Qg, const __half* __restrict__ KM,
    const __half* __restrict__ Vg, const float* __restrict__ kbias,
    __half* __restrict__ y)
{
    extern __shared__ __align__(16) __half smha[];
    __half* ks_base = smha;                       // 3 stages (KM2 tiles)
    __half* vs_base = smha + 3 * KVST;            // 3 stages
    float* kbt_base = (float*)(smha + 6 * KVST);  // 3 x 64

    const int bh = blockIdx.x, qt = blockIdx.y;   // qt: 128-row tile
    const int b = bh >> 2, h = bh & 3;
    const int t = threadIdx.x;
    const int wid = t >> 5, lane = t & 31;
    const int lr4 = lane >> 2, lc4 = lane & 3;
    const int g8 = lane >> 3, l8 = lane & 7;
    const int r0 = wid * 16;

    auto prefetch = [&](int kt, int st) {
        const __half* kg = KM + ((size_t)bh * Nn + kt * 64) * HDn;
        const __half* vg = Vg + ((size_t)bh * Nn + kt * 64) * HDn;
        __half* ksb = ks_base + st * KVST;
        __half* vsb = vs_base + st * KVST;
#pragma unroll
        for (int i = 0; i < 6; i++) {
            const int ch = t + i * 256;
            const int r = ch / 24, c = ch % 24;
            cp_async16(&ksb[r * KSs + c * 8], kg + r * HDn + c * 8);
            cp_async16(&vsb[r * KSs + c * 8], vg + r * HDn + c * 8);
        }
        if (t < 16) cp_async16(&kbt_base[st * 64 + t * 4],
                               kbias + (size_t)bh * Nn + kt * 64 + t * 4);
    };

    prefetch(0, 0); cp_commit();
    prefetch(1, 1); cp_commit();

    uint32_t qa[12][4];
    {
        const __half* qb = Qg + ((size_t)bh * Nn + qt * 128) * HDn;
#pragma unroll
        for (int k16 = 0; k16 < 12; k16++) {
            const int kk = k16 * 16;
            qa[k16][0] = *(const uint32_t*)&qb[(r0 + lr4)     * HDn + kk + 2 * lc4];
            qa[k16][1] = *(const uint32_t*)&qb[(r0 + lr4 + 8) * HDn + kk + 2 * lc4];
            qa[k16][2] = *(const uint32_t*)&qb[(r0 + lr4)     * HDn + kk + 8 + 2 * lc4];
            qa[k16][3] = *(const uint32_t*)&qb[(r0 + lr4 + 8) * HDn + kk + 8 + 2 * lc4];
        }
    }

    float O[24][4];
#pragma unroll
    for (int nt = 0; nt < 24; nt++)
#pragma unroll
        for (int q = 0; q < 4; q++) O[nt][q] = 0.f;
    float mr0 = -1e30f, mr1 = -1e30f, l0 = 0.f, l1 = 0.f;

    for (int kt = 0; kt < Nn / 64; kt++) {
        cp_wait<1>();
        __syncthreads();
        if (kt + 2 < Nn / 64) prefetch(kt + 2, (kt + 2) % 3);
        cp_commit();

        const int st = kt % 3;
        const uint32_t ks_u = (uint32_t)__cvta_generic_to_shared(ks_base + st * KVST);
        const uint32_t vs_u = (uint32_t)__cvta_generic_to_shared(vs_base + st * KVST);
        const float* kbt = kbt_base + st * 64;

        float s[8][4];
#pragma unroll
        for (int nt = 0; nt < 8; nt++)
#pragma unroll
            for (int q = 0; q < 4; q++) s[nt][q] = 0.f;
#pragma unroll
        for (int k16 = 0; k16 < 12; k16++) {
            const int kk = k16 * 16;
            uint32_t bf[8][2];
#pragma unroll
            for (int p = 0; p < 4; p++) {
                const int row = p * 16 + (g8 >> 1) * 8 + l8;
                const int col = kk + (g8 & 1) * 8;
                ldsm4(bf[2 * p][0], bf[2 * p][1], bf[2 * p + 1][0], bf[2 * p + 1][1],
                      ks_u + (row * KSs + col) * 2);
            }
#pragma unroll
            for (int nt = 0; nt < 8; nt++)
                mma16h(s[nt], qa[k16][0], qa[k16][1], qa[k16][2], qa[k16][3],
                       bf[nt][0], bf[nt][1]);
        }

        float pm0 = -1e30f, pm1 = -1e30f;
#pragma unroll
        for (int nt = 0; nt < 8; nt++) {
            const int col = nt * 8 + 2 * lc4;
            const float kb0 = kbt[col], kb1 = kbt[col + 1];
            s[nt][0] += kb0; s[nt][1] += kb1;
            s[nt][2] += kb0; s[nt][3] += kb1;
            pm0 = fmaxf(pm0, fmaxf(s[nt][0], s[nt][1]));
            pm1 = fmaxf(pm1, fmaxf(s[nt][2], s[nt][3]));
        }
        pm0 = fmaxf(pm0, __shfl_xor_sync(0xffffffffu, pm0, 1));
        pm0 = fmaxf(pm0, __shfl_xor_sync(0xffffffffu, pm0, 2));
        pm1 = fmaxf(pm1, __shfl_xor_sync(0xffffffffu, pm1, 1));
        pm1 = fmaxf(pm1, __shfl_xor_sync(0xffffffffu, pm1, 2));
        const float mn0 = fmaxf(mr0, pm0), mn1 = fmaxf(mr1, pm1);
        const float cor0 = __expf(mr0 - mn0), cor1 = __expf(mr1 - mn1);
        mr0 = mn0; mr1 = mn1;

        uint32_t pa[4][4];
        float q0 = 0.f, q1 = 0.f;
#pragma unroll
        for (int j = 0; j < 4; j++) {
#pragma unroll
            for (int hh = 0; hh < 2; hh++) {
                const int nt = 2 * j + hh;
                const float e0 = __expf(s[nt][0] - mn0);
                const float e1 = __expf(s[nt][1] - mn0);
                const float e2 = __expf(s[nt][2] - mn1);
                const float e3 = __expf(s[nt][3] - mn1);
                q0 += e0 + e1; q1 += e2 + e3;
                pa[j][2 * hh]     = h2u(__floats2half2_rn(e0, e1));
                pa[j][2 * hh + 1] = h2u(__floats2half2_rn(e2, e3));
            }
        }
        q0 += __shfl_xor_sync(0xffffffffu, q0, 1);
        q0 += __shfl_xor_sync(0xffffffffu, q0, 2);
        q1 += __shfl_xor_sync(0xffffffffu, q1, 1);
        q1 += __shfl_xor_sync(0xffffffffu, q1, 2);
        l0 = l0 * cor0 + q0;
        l1 = l1 * cor1 + q1;
#pragma unroll
        for (int nt = 0; nt < 24; nt++) {
            O[nt][0] *= cor0; O[nt][1] *= cor0;
            O[nt][2] *= cor1; O[nt][3] *= cor1;
        }

#pragma unroll
        for (int j = 0; j < 4; j++) {
            const int kk = j * 16;
#pragma unroll
            for (int p = 0; p < 12; p++) {
                const int rowv = kk + (g8 & 1) * 8 + l8;
                const int colv = p * 16 + (g8 >> 1) * 8;
                uint32_t b0A, b1A, b0B, b1B;
                ldsm4t(b0A, b1A, b0B, b1B, vs_u + (rowv * KSs + colv) * 2);
                mma16h(O[2 * p],     pa[j][0], pa[j][1], pa[j][2], pa[j][3], b0A, b1A);
                mma16h(O[2 * p + 1], pa[j][0], pa[j][1], pa[j][2], pa[j][3], b0B, b1B);
            }
        }
    }

    const float i0v = 1.0f / l0, i1v = 1.0f / l1;
    const int nrow0 = qt * 128 + r0 + lr4;
    __half* y0 = y + (size_t)(b * Nn + nrow0) * Cdim + h * HDn;
    __half* y1 = y0 + 8 * Cdim;
#pragma unroll
    for (int nt = 0; nt < 24; nt++) {
        const int col = nt * 8 + 2 * lc4;
        *(__half2*)&y0[col] = __floats2half2_rn(O[nt][0] * i0v, O[nt][1] * i0v);
        *(__half2*)&y1[col] = __floats2half2_rn(O[nt][2] * i1v, O[nt][3] * i1v);
    }
}

// ---------------- fused LN2 + RBF + fc + residual -> out (2 rows / warp-iter) --------
// centers stored as half in smem; dots via HFMA2. fc_w^T stays fp32.
constexpr int RBF_SMEM_BYTES = CEN * Cdim * 4 + CEN * Cdim * 2 + 2 * CEN * 4;  // 92320 B

__global__ __launch_bounds__(256) void rbf_final_kernel(
    const float* __restrict__ x1, const float* __restrict__ n2w,
    const float* __restrict__ n2b, const float* __restrict__ centers,
    const float* __restrict__ beta, const float* __restrict__ fcw,
    float* __restrict__ out)
{
    extern __shared__ __align__(16) float rsm[];
    float*  fwT = rsm;                             // [CEN][Cdim] fp32 fc_w transposed
    __half* csh = (__half*)(rsm + CEN * Cdim);     // [CEN][Cdim] half centers
    float*  cn  = (float*)(csh + CEN * Cdim);      // [CEN]
    float*  bt  = cn + CEN;                        // [CEN]
    const int t = threadIdx.x;
    for (int i = t; i < CEN * Cdim; i += 256) {
        const int j = i / Cdim, c = i % Cdim;
        fwT[i] = fcw[c * CEN + j];
        csh[i] = __float2half(centers[i]);
    }
    __syncthreads();
    if (t < CEN) {
        float s = 0.f;
        for (int k = 0; k < Cdim; k++) {
            const float cv = centers[t * Cdim + k];
            s += cv * cv;
        }
        cn[t] = s;
        bt[t] = beta[t];
    }
    __syncthreads();
    const int wid = t >> 5, lane = t & 31;
    const float4* w4 = (const float4*)n2w;
    const float4* b4 = (const float4*)n2b;

    for (int rr = 0; rr < 4; rr++) {
        const int row0 = blockIdx.x * 64 + wid * 8 + rr * 2;
        const float4* xr0 = (const float4*)(x1 + (size_t)row0 * Cdim);
        const float4* xr1 = (const float4*)(x1 + (size_t)(row0 + 1) * Cdim);

        float hv0[24], hv1[24];
        __half2 hh0[12], hh1[12];
        float a0, a1;
        {   // row0 LN
            float4 v[6];
            float s = 0.f, s2 = 0.f;
#pragma unroll
            for (int i = 0; i < 6; i++) {
                v[i] = xr0[lane + i * 32];
                s  += v[i].x + v[i].y + v[i].z + v[i].w;
                s2 += v[i].x * v[i].x + v[i].y * v[i].y + v[i].z * v[i].z + v[i].w * v[i].w;
            }
            s = warpsum32(s); s2 = warpsum32(s2);
            const float mu = s * (1.0f / Cdim);
            const float rs = rsqrtf(s2 * (1.0f / Cdim) - mu * mu + EPSv);
            float a = 0.f;
#pragma unroll
            for (int i = 0; i < 6; i++) {
                const int idx = lane + i * 32;
                const float4 wv = w4[idx], bv = b4[idx];
                hv0[4*i+0] = (v[i].x - mu) * rs * wv.x + bv.x;
                hv0[4*i+1] = (v[i].y - mu) * rs * wv.y + bv.y;
                hv0[4*i+2] = (v[i].z - mu) * rs * wv.z + bv.z;
                hv0[4*i+3] = (v[i].w - mu) * rs * wv.w + bv.w;
                a += hv0[4*i]*hv0[4*i] + hv0[4*i+1]*hv0[4*i+1]
                   + hv0[4*i+2]*hv0[4*i+2] + hv0[4*i+3]*hv0[4*i+3];
                hh0[2*i]   = __floats2half2_rn(hv0[4*i],   hv0[4*i+1]);
                hh0[2*i+1] = __floats2half2_rn(hv0[4*i+2], hv0[4*i+3]);
            }
            a0 = warpsum32(a);
        }
        {   // row1 LN
            float4 v[6];
            float s = 0.f, s2 = 0.f;
#pragma unroll
            for (int i = 0; i < 6; i++) {
                v[i] = xr1[lane + i * 32];
                s  += v[i].x + v[i].y + v[i].z + v[i].w;
                s2 += v[i].x * v[i].x + v[i].y * v[i].y + v[i].z * v[i].z + v[i].w * v[i].w;
            }
            s = warpsum32(s); s2 = warpsum32(s2);
            const float mu = s * (1.0f / Cdim);
            const float rs = rsqrtf(s2 * (1.0f / Cdim) - mu * mu + EPSv);
            float a = 0.f;
#pragma unroll
            for (int i = 0; i < 6; i++) {
                const int idx = lane + i * 32;
                const float4 wv = w4[idx], bv = b4[idx];
                hv1[4*i+0] = (v[i].x - mu) * rs * wv.x + bv.x;
                hv1[4*i+1] = (v[i].y - mu) * rs * wv.y + bv.y;
                hv1[4*i+2] = (v[i].z - mu) * rs * wv.z + bv.z;
                hv1[4*i+3] = (v[i].w - mu) * rs * wv.w + bv.w;
                a += hv1[4*i]*hv1[4*i] + hv1[4*i+1]*hv1[4*i+1]
                   + hv1[4*i+2]*hv1[4*i+2] + hv1[4*i+3]*hv1[4*i+3];
                hh1[2*i]   = __floats2half2_rn(hv1[4*i],   hv1[4*i+1]);
                hh1[2*i+1] = __floats2half2_rn(hv1[4*i+2], hv1[4*i+3]);
            }
            a1 = warpsum32(a);
        }

        // rbf values for both rows: HFMA2 dots against half centers
        float rj0[CEN], rj1[CEN];
#pragma unroll
        for (int j = 0; j < CEN; j++) {
            const __half* cj = csh + j * Cdim;
            __half2 acc0 = __floats2half2_rn(0.f, 0.f);
            __half2 acc1 = acc0;
#pragma unroll
            for (int i = 0; i < 6; i++) {
                const int idx = lane + i * 32;
                const uint2 cc = *(const uint2*)&cj[4 * idx];
                const __half2 ca = u2h(cc.x), cb = u2h(cc.y);
                acc0 = __hfma2(hh0[2*i], ca, acc0);
                acc0 = __hfma2(hh0[2*i+1], cb, acc0);
                acc1 = __hfma2(hh1[2*i], ca, acc1);
                acc1 = __hfma2(hh1[2*i+1], cb, acc1);
            }
            const float2 f0 = __half22float2(acc0);
            const float2 f1 = __half22float2(acc1);
            float d0 = warpsum32(f0.x + f0.y);
            float d1 = warpsum32(f1.x + f1.y);
            rj0[j] = __expf(-bt[j] * (a0 - 2.0f * d0 + cn[j]));
            rj1[j] = __expf(-bt[j] * (a1 - 2.0f * d1 + cn[j]));
        }

        // out = x1 + rbf @ fc_w^T  (fp32 fwT, shared reads for both rows)
        float4* o0row = (float4*)(out + (size_t)row0 * Cdim);
        float4* o1row = (float4*)(out + (size_t)(row0 + 1) * Cdim);
#pragma unroll
        for (int i = 0; i < 6; i++) {
            const int idx = lane + i * 32;
            float4 o0 = xr0[idx];
            float4 o1 = xr1[idx];
#pragma unroll
            for (int j = 0; j < CEN; j++) {
                const float4 fv = *(const float4*)&fwT[j * Cdim + 4 * idx];
                o0.x += rj0[j] * fv.x; o0.y += rj0[j] * fv.y;
                o0.z += rj0[j] * fv.z; o0.w += rj0[j] * fv.w;
                o1.x += rj1[j] * fv.x; o1.y += rj1[j] * fv.y;
                o1.z += rj1[j] * fv.z; o1.w += rj1[j] * fv.w;
            }
            o0row[idx] = o0;
            o1row[idx] = o1;
        }
    }
}

// ---------------- launcher ----------------
extern "C" void kernel_launch(void* const* d_in, const int* in_sizes, int n_in,
                              void* d_out, int out_size)
{
    (void)in_sizes; (void)n_in; (void)out_size;
    const float* x     = (const float*)d_in[0];
    const float* n1w   = (const float*)d_in[1];
    const float* n1b   = (const float*)d_in[2];
    const float* qkvw  = (const float*)d_in[3];
    const float* Mmat  = (const float*)d_in[4];
    const float* scale = (const float*)d_in[5];
    const float* projw = (const float*)d_in[6];
    const float* projb = (const float*)d_in[7];
    const float* n2w   = (const float*)d_in[8];
    const float* n2b   = (const float*)d_in[9];
    const float* cent  = (const float*)d_in[10];
    const float* beta  = (const float*)d_in[11];
    const float* fcw   = (const float*)d_in[12];
    float* out = (float*)d_out;

    __half *hP, *qwP, *pwP, *QgP, *KgP, *VgP, *KMP, *MhP, *yP;
    float *kbpP, *kbP, *x1P;
    cudaGetSymbolAddress((void**)&hP,   g_h);
    cudaGetSymbolAddress((void**)&qwP,  g_qkvwr);
    cudaGetSymbolAddress((void**)&pwP,  g_projwr);
    cudaGetSymbolAddress((void**)&QgP,  g_Qg);
    cudaGetSymbolAddress((void**)&KgP,  g_Kg);
    cudaGetSymbolAddress((void**)&VgP,  g_Vg);
    cudaGetSymbolAddress((void**)&KMP,  g_KM);
    cudaGetSymbolAddress((void**)&MhP,  g_Mh);
    cudaGetSymbolAddress((void**)&kbpP, g_kbp);
    cudaGetSymbolAddress((void**)&kbP,  g_kb);
    cudaGetSymbolAddress((void**)&yP,   g_y);
    cudaGetSymbolAddress((void**)&x1P,  g_x1);

    constexpr int GS128 = 3 * (128 + 128) * 64 * 2;   // 98304 B
    constexpr int GS64  = 3 * (128 + 64) * 64 * 2;    // 73728 B
    cudaFuncSetAttribute(gemm_h<128, 1>, cudaFuncAttributeMaxDynamicSharedMemorySize, GS128);
    cudaFuncSetAttribute(gemm_h<128, 2>, cudaFuncAttributeMaxDynamicSharedMemorySize, GS128);
    cudaFuncSetAttribute(gemm_h<64, 3>,  cudaFuncAttributeMaxDynamicSharedMemorySize, GS64);
    cudaFuncSetAttribute(attn_tc_kernel, cudaFuncAttributeMaxDynamicSharedMemorySize, ATT_SMEM);
    cudaFuncSetAttribute(rbf_final_kernel, cudaFuncAttributeMaxDynamicSharedMemorySize, RBF_SMEM_BYTES);

    // streams/events for prep overlap (created once; reused across calls)
    static cudaStream_t sA = nullptr, sB = nullptr;
    static cudaEvent_t  eF = nullptr, eA = nullptr, eB = nullptr;
    if (!sA) {
        cudaStreamCreateWithFlags(&sA, cudaStreamNonBlocking);
        cudaStreamCreateWithFlags(&sB, cudaStreamNonBlocking);
        cudaEventCreateWithFlags(&eF, cudaEventDisableTiming);
        cudaEventCreateWithFlags(&eA, cudaEventDisableTiming);
        cudaEventCreateWithFlags(&eB, cudaEventDisableTiming);
    }

    // fork prep work onto side streams
    cudaEventRecord(eF, 0);
    cudaStreamWaitEvent(sA, eF, 0);
    cudaStreamWaitEvent(sB, eF, 0);
    half_copy4_kernel<<<512, 256, 0, sA>>>((const float4*)qkvw, qwP, 3 * Cdim * Cdim / 4);
    cudaEventRecord(eA, sA);
    half_copy4_kernel<<<256, 256, 0, sB>>>((const float4*)projw, pwP, Cdim * Cdim / 4);
    scale_m_kernel<<<(HDn * HDn + 255) / 256, 256, 0, sB>>>(Mmat, scale, MhP);
    cudaEventRecord(eB, sB);

    // 1) LN1 (half out) — overlaps the weight conversions
    ln1_kernel<<<Sn / 16, 256>>>(x, n1w, n1b, hP);
    // join qkv weights
    cudaStreamWaitEvent(0, eA, 0);
    // 2) qkv GEMM fused with gather -> Qg/Kg/Vg (half)
    gemm_h<128, 1><<<dim3(3 * Cdim / 128, Sn / 128), 256, GS128>>>(
        hP, qwP, QgP, KgP, VgP, Sn, 3 * Cdim, Cdim, nullptr, nullptr, nullptr);
    // join Mh (+proj weights, conservative)
    cudaStreamWaitEvent(0, eB, 0);
    // 3) KM2 = K @ (2*scale*M)^T with fused kbias partials
    gemm_h<64, 3><<<dim3(HDn / 64, BHn * Nn / 128), 256, GS64>>>(
        KgP, MhP, KMP, nullptr, nullptr, BHn * Nn, HDn, HDn, nullptr, nullptr, kbpP);
    // 4) kb = -0.5 * sum(partials)
    kb_reduce_kernel<<<(BHn * Nn + 255) / 256, 256>>>(kbpP, kbP);
    // 5) fp16 flash attention (q . KM2 + kb) -> y (half)
    attn_tc_kernel<<<dim3(BHn, Nn / 128), 256, ATT_SMEM>>>(QgP, KMP, VgP, kbP, yP);
    // 6) x1 = x + y @ proj_w^T + proj_b (fp32 out)
    gemm_h<128, 2><<<dim3(Cdim / 128, Sn / 128), 256, GS128>>>(
        yP, pwP, x1P, nullptr, nullptr, Sn, Cdim, Cdim, projb, x, nullptr);
    // 7) fused LN2 + RBF + fc + residual -> out
    rbf_final_kernel<<<Sn / 64, 256, RBF_SMEM_BYTES>>>(x1P, n2w, n2b, cent, beta, fcw, out);
}

// round 14
// speedup vs baseline: 1.0135x; 1.0135x over previous
#include <cuda_runtime.h>
#include <cuda_fp16.h>
#include <cstdint>

// ---------------- problem constants ----------------
constexpr int Cdim = 768;
constexpr int Bn   = 8;
constexpr int Nn   = 1024;
constexpr int HDn  = 192;            // head dim
constexpr int Sn   = Bn * Nn;        // 8192 rows
constexpr int BHn  = Bn * 4;         // 32
constexpr int CEN  = 20;
constexpr float EPSv = 1e-5f;

// ---------------- scratch (device globals; no allocation allowed) ----------------
__device__ __half g_h     [Sn * Cdim];
__device__ __half g_qkvwr [3 * Cdim * Cdim];
__device__ __half g_projwr[Cdim * Cdim];
__device__ __half g_Qg  [BHn * Nn * HDn];
__device__ __half g_Kg  [BHn * Nn * HDn];
__device__ __half g_Vg  [BHn * Nn * HDn];
__device__ __half g_KM  [BHn * Nn * HDn];   // KM2 = K @ (2*scale*M)^T
__device__ __half g_Mh  [HDn * HDn];        // 2*scale*M (half)
__device__ float  g_kbp [3 * BHn * Nn];     // kbias partials (one per N-block)
__device__ __half g_y   [Sn * Cdim];
__device__ float  g_x1  [Sn * Cdim];

// ---------------- helpers ----------------
__device__ __forceinline__ float warpsum32(float v) {
#pragma unroll
    for (int o = 16; o >= 1; o >>= 1) v += __shfl_xor_sync(0xffffffffu, v, o);
    return v;
}
__device__ __forceinline__ uint32_t h2u(__half2 h) {
    return *reinterpret_cast<uint32_t*>(&h);
}
__device__ __forceinline__ void mma16h(float* c,
    uint32_t a0, uint32_t a1, uint32_t a2, uint32_t a3, uint32_t b0, uint32_t b1)
{
    asm volatile("mma.sync.aligned.m16n8k16.row.col.f32.f16.f16.f32 "
        "{%0,%1,%2,%3}, {%4,%5,%6,%7}, {%8,%9}, {%0,%1,%2,%3};"
        : "+f"(c[0]), "+f"(c[1]), "+f"(c[2]), "+f"(c[3])
        : "r"(a0), "r"(a1), "r"(a2), "r"(a3), "r"(b0), "r"(b1));
}
__device__ __forceinline__ void ldsm4(uint32_t& r0, uint32_t& r1, uint32_t& r2, uint32_t& r3,
                                      uint32_t addr)
{
    asm volatile("ldmatrix.sync.aligned.m8n8.x4.shared.b16 {%0,%1,%2,%3}, [%4];"
        : "=r"(r0), "=r"(r1), "=r"(r2), "=r"(r3) : "r"(addr));
}
__device__ __forceinline__ void ldsm4t(uint32_t& r0, uint32_t& r1, uint32_t& r2, uint32_t& r3,
                                       uint32_t addr)
{
    asm volatile("ldmatrix.sync.aligned.m8n8.x4.trans.shared.b16 {%0,%1,%2,%3}, [%4];"
        : "=r"(r0), "=r"(r1), "=r"(r2), "=r"(r3) : "r"(addr));
}
__device__ __forceinline__ void cp_async16(void* smem, const void* gmem) {
    uint32_t s = (uint32_t)__cvta_generic_to_shared(smem);
    asm volatile("cp.async.cg.shared.global [%0], [%1], 16;\n" :: "r"(s), "l"(gmem));
}
__device__ __forceinline__ void cp_commit() {
    asm volatile("cp.async.commit_group;\n");
}
template<int N>
__device__ __forceinline__ void cp_wait() {
    asm volatile("cp.async.wait_group %0;\n" :: "n"(N));
}

// ---------------- LayerNorm (LN1): warp per row, half output (R12 version) ----------
__global__ __launch_bounds__(256) void ln1_kernel(
    const float* __restrict__ x, const float* __restrict__ w,
    const float* __restrict__ b, __half* __restrict__ out)
{
    const int row  = blockIdx.x * 8 + (threadIdx.x >> 5);
    const int lane = threadIdx.x & 31;
    const float4* xr = (const float4*)(x + (size_t)row * Cdim);
    float4 v[6];
    float s = 0.f, s2 = 0.f;
#pragma unroll
    for (int i = 0; i < 6; i++) {
        v[i] = xr[lane + i * 32];
        s  += v[i].x + v[i].y + v[i].z + v[i].w;
        s2 += v[i].x * v[i].x + v[i].y * v[i].y + v[i].z * v[i].z + v[i].w * v[i].w;
    }
    s = warpsum32(s); s2 = warpsum32(s2);
    const float mu  = s * (1.0f / Cdim);
    const float var = s2 * (1.0f / Cdim) - mu * mu;
    const float rs  = rsqrtf(var + EPSv);
    const float4* w4 = (const float4*)w;
    const float4* b4 = (const float4*)b;
#pragma unroll
    for (int i = 0; i < 6; i++) {
        const int idx = lane + i * 32;
        const float4 wv = w4[idx], bv = b4[idx];
        __half* orow = out + (size_t)row * Cdim + 4 * idx;
        *(__half2*)&orow[0] = __floats2half2_rn((v[i].x - mu) * rs * wv.x + bv.x,
                                                (v[i].y - mu) * rs * wv.y + bv.y);
        *(__half2*)&orow[2] = __floats2half2_rn((v[i].z - mu) * rs * wv.z + bv.z,
                                                (v[i].w - mu) * rs * wv.w + bv.w);
    }
}

// ---------------- f32 -> f16 copy (vectorized) ----------------
__global__ __launch_bounds__(256) void half_copy4_kernel(
    const float4* __restrict__ src, __half* __restrict__ dst, int n4)
{
    for (int i = blockIdx.x * 256 + threadIdx.x; i < n4; i += gridDim.x * 256) {
        const float4 v = src[i];
        *(__half2*)&dst[4 * i]     = __floats2half2_rn(v.x, v.y);
        *(__half2*)&dst[4 * i + 2] = __floats2half2_rn(v.z, v.w);
    }
}

// ---------------- Mh = 2*scale*M (half, same layout) ----------------
__global__ __launch_bounds__(256) void scale_m_kernel(
    const float* __restrict__ M, const float* __restrict__ scale_p,
    __half* __restrict__ Mh)
{
    const int i = blockIdx.x * 256 + threadIdx.x;
    if (i >= HDn * HDn) return;
    Mh[i] = __float2half(2.0f * scale_p[0] * M[i]);
}

// ---------------- 3-stage pipelined fp16 NT GEMM: C = A[M,K] * B[N,K]^T ----------------
// MODE 0: half store. MODE 1: qkv scatter -> Q/K/V half [BH][N][HD]. MODE 2: fp32 +bias+resid.
// MODE 3: half store + kbias partials kbp[bx*Md + row] = sum_n A[row,n]*acc[row,n].
template<int BN, int MODE>
__global__ __launch_bounds__(256) void gemm_h(
    const __half* __restrict__ A, const __half* __restrict__ B, void* __restrict__ Cv,
    __half* __restrict__ C2, __half* __restrict__ C3,
    int Md, int Nd, int Kd,
    const float* __restrict__ bias, const float* __restrict__ resid,
    float* __restrict__ kbp)
{
    constexpr int BM = 128, BK = 64;
    constexpr int WM = (BN == 128) ? 2 : 4;
    constexpr int WN = 8 / WM;
    constexpr int WTM = BM / WM, WTN = BN / WN;
    constexpr int MT = WTM / 16, NT = WTN / 8;
    constexpr int ASTG = BM * BK;
    constexpr int BSTG = BN * BK;

    extern __shared__ __align__(16) __half smh[];
    __half* As = smh;                 // 3 stages
    __half* Bs = smh + 3 * ASTG;      // 3 stages

    const int t = threadIdx.x;
    const int wid = t >> 5, lane = t & 31;
    const int wm = wid % WM, wn = wid / WM;
    const int lr4 = lane >> 2, lc4 = lane & 3;
    const int g8 = lane >> 3, l8 = lane & 7;
    const int m0 = blockIdx.y * BM, n0 = blockIdx.x * BN;

    const __half* Ab = A + (size_t)m0 * Kd;
    const __half* Bb = B + (size_t)n0 * Kd;

    auto prefetch = [&](int kt, int st) {
        const __half* Ag = Ab + kt * BK;
        const __half* Bg = Bb + kt * BK;
#pragma unroll
        for (int i = 0; i < BM / 32; i++) {
            const int ch = t + i * 256;
            const int r = ch >> 3, c = ch & 7;
            cp_async16(&As[st * ASTG + (r * 8 + (c ^ (r & 7))) * 8], Ag + (size_t)r * Kd + c * 8);
        }
#pragma unroll
        for (int i = 0; i < BN / 32; i++) {
            const int ch = t + i * 256;
            const int r = ch >> 3, c = ch & 7;
            cp_async16(&Bs[st * BSTG + (r * 8 + (c ^ (r & 7))) * 8], Bg + (size_t)r * Kd + c * 8);
        }
    };

    float acc[MT][NT][4];
#pragma unroll
    for (int i = 0; i < MT; i++)
#pragma unroll
        for (int j = 0; j < NT; j++)
#pragma unroll
            for (int q = 0; q < 4; q++) acc[i][j][q] = 0.f;

    const int nK = Kd / BK;
    prefetch(0, 0); cp_commit();
    prefetch(1, 1); cp_commit();

    for (int kt = 0; kt < nK; kt++) {
        cp_wait<1>();
        __syncthreads();
        if (kt + 2 < nK) prefetch(kt + 2, (kt + 2) % 3);
        cp_commit();

        const int st = kt % 3;
        const uint32_t Au = (uint32_t)__cvta_generic_to_shared(As + st * ASTG);
        const uint32_t Bu = (uint32_t)__cvta_generic_to_shared(Bs + st * BSTG);

#pragma unroll
        for (int k16 = 0; k16 < BK / 16; k16++) {
            uint32_t bf[NT][2];
#pragma unroll
            for (int p = 0; p < NT / 2; p++) {
                const int row = wn * WTN + p * 16 + (g8 >> 1) * 8 + l8;
                const int ch  = (2 * k16 + (g8 & 1)) ^ l8;
                ldsm4(bf[2 * p][0], bf[2 * p][1], bf[2 * p + 1][0], bf[2 * p + 1][1],
                      Bu + (row * 8 + ch) * 16);
            }
#pragma unroll
            for (int mt = 0; mt < MT; mt++) {
                const int rowA = wm * WTM + mt * 16 + (g8 & 1) * 8 + l8;
                const int chA  = (2 * k16 + (g8 >> 1)) ^ l8;
                uint32_t a0, a1, a2, a3;
                ldsm4(a0, a1, a2, a3, Au + (rowA * 8 + chA) * 16);
#pragma unroll
                for (int nt = 0; nt < NT; nt++)
                    mma16h(acc[mt][nt], a0, a1, a2, a3, bf[nt][0], bf[nt][1]);
            }
        }
    }

    float part[MT][2];
    if (MODE == 3) {
#pragma unroll
        for (int mt = 0; mt < MT; mt++) { part[mt][0] = 0.f; part[mt][1] = 0.f; }
    }

#pragma unroll
    for (int mt = 0; mt < MT; mt++) {
        const int mbase = m0 + wm * WTM + mt * 16 + lr4;
#pragma unroll
        for (int nt = 0; nt < NT; nt++) {
            const int n = n0 + wn * WTN + nt * 8 + 2 * lc4;
            if (MODE == 0 || MODE == 3) {
                __half* C = (__half*)Cv;
                *(__half2*)&C[(size_t)mbase * Nd + n] =
                    __floats2half2_rn(acc[mt][nt][0], acc[mt][nt][1]);
                *(__half2*)&C[(size_t)(mbase + 8) * Nd + n] =
                    __floats2half2_rn(acc[mt][nt][2], acc[mt][nt][3]);
                if (MODE == 3) {
                    const float2 k0 = __half22float2(*(const __half2*)&A[(size_t)mbase * Kd + n]);
                    const float2 k1 = __half22float2(*(const __half2*)&A[(size_t)(mbase + 8) * Kd + n]);
                    part[mt][0] += k0.x * acc[mt][nt][0] + k0.y * acc[mt][nt][1];
                    part[mt][1] += k1.x * acc[mt][nt][2] + k1.y * acc[mt][nt][3];
                }
            } else if (MODE == 1) {
                const int which = n / Cdim;
                const int rem = n % Cdim;
                const int h = rem / HDn, d = rem % HDn;
                __half* dst = (which == 0) ? (__half*)Cv : (which == 1) ? C2 : C3;
#pragma unroll
                for (int rr = 0; rr < 2; rr++) {
                    const int m = mbase + rr * 8;
                    const int b = m >> 10, nr = m & 1023;
                    const size_t di = ((size_t)((b << 2) + h) * Nn + nr) * HDn + d;
                    *(__half2*)&dst[di] =
                        __floats2half2_rn(acc[mt][nt][rr * 2], acc[mt][nt][rr * 2 + 1]);
                }
            } else {
                float* C = (float*)Cv;
                const float b0 = bias[n], b1 = bias[n + 1];
                const size_t i0 = (size_t)mbase * Nd + n;
                const size_t i1 = (size_t)(mbase + 8) * Nd + n;
                *(float2*)&C[i0] = make_float2(acc[mt][nt][0] + b0 + resid[i0],
                                               acc[mt][nt][1] + b1 + resid[i0 + 1]);
                *(float2*)&C[i1] = make_float2(acc[mt][nt][2] + b0 + resid[i1],
                                               acc[mt][nt][3] + b1 + resid[i1 + 1]);
            }
        }
    }

    if (MODE == 3) {
        float pr[MT][2];
#pragma unroll
        for (int mt = 0; mt < MT; mt++)
#pragma unroll
            for (int sr = 0; sr < 2; sr++) {
                float p = part[mt][sr];
                p += __shfl_xor_sync(0xffffffffu, p, 1);
                p += __shfl_xor_sync(0xffffffffu, p, 2);
                pr[mt][sr] = p;
            }
        __syncthreads();
        float* sred = (float*)smh;
        if (wn == 0 && lc4 == 0) {
#pragma unroll
            for (int mt = 0; mt < MT; mt++)
#pragma unroll
                for (int sr = 0; sr < 2; sr++)
                    sred[wm * WTM + mt * 16 + sr * 8 + lr4] = pr[mt][sr];
        }
        __syncthreads();
        if (wn == 1 && lc4 == 0) {
#pragma unroll
            for (int mt = 0; mt < MT; mt++)
#pragma unroll
                for (int sr = 0; sr < 2; sr++) {
                    const int rl = wm * WTM + mt * 16 + sr * 8 + lr4;
                    kbp[(size_t)blockIdx.x * Md + m0 + rl] = sred[rl] + pr[mt][sr];
                }
        }
    }
}

// ---------------- fp16 flash attention (3-stage): S = q . KM2 - 0.5*sum(kbp) --------
// kbias partials combined at the register read point (no separate reduce kernel).
constexpr int KSs = 200;        // K/V smem stride (halfs)
constexpr int KVST = 64 * KSs;  // halfs per stage
constexpr int ATT_SMEM = 3 * 2 * KVST * 2 + 3 * 192 * 4;   // 155904 B

__global__ __launch_bounds__(256, 1) void attn_tc_kernel(
    const __half* __restrict__ Qg, const __half* __restrict__ KM,
    const __half* __restrict__ Vg, const float* __restrict__ kbp,
    __half* __restrict__ y)
{
    extern __shared__ __align__(16) __half smha[];
    __half* ks_base = smha;                       // 3 stages (KM2 tiles)
    __half* vs_base = smha + 3 * KVST;            // 3 stages
    float* kbt_base = (float*)(smha + 6 * KVST);  // 3 stages x [3][64] partials

    const int bh = blockIdx.x, qt = blockIdx.y;   // qt: 128-row tile
    const int b = bh >> 2, h = bh & 3;
    const int t = threadIdx.x;
    const int wid = t >> 5, lane = t & 31;
    const int lr4 = lane >> 2, lc4 = lane & 3;
    const int g8 = lane >> 3, l8 = lane & 7;
    const int r0 = wid * 16;

    auto prefetch = [&](int kt, int st) {
        const __half* kg = KM + ((size_t)bh * Nn + kt * 64) * HDn;
        const __half* vg = Vg + ((size_t)bh * Nn + kt * 64) * HDn;
        __half* ksb = ks_base + st * KVST;
        __half* vsb = vs_base + st * KVST;
#pragma unroll
        for (int i = 0; i < 6; i++) {
            const int ch = t + i * 256;
            const int r = ch / 24, c = ch % 24;
            cp_async16(&ksb[r * KSs + c * 8], kg + r * HDn + c * 8);
            cp_async16(&vsb[r * KSs + c * 8], vg + r * HDn + c * 8);
        }
        if (t < 48) {   // 3 partial arrays x 64 floats
            const int p = t >> 4, o = (t & 15) * 4;
            cp_async16(&kbt_base[st * 192 + p * 64 + o],
                       kbp + (size_t)p * (BHn * Nn) + (size_t)bh * Nn + kt * 64 + o);
        }
    };

    prefetch(0, 0); cp_commit();
    prefetch(1, 1); cp_commit();

    uint32_t qa[12][4];
    {
        const __half* qb = Qg + ((size_t)bh * Nn + qt * 128) * HDn;
#pragma unroll
        for (int k16 = 0; k16 < 12; k16++) {
            const int kk = k16 * 16;
            qa[k16][0] = *(const uint32_t*)&qb[(r0 + lr4)     * HDn + kk + 2 * lc4];
            qa[k16][1] = *(const uint32_t*)&qb[(r0 + lr4 + 8) * HDn + kk + 2 * lc4];
            qa[k16][2] = *(const uint32_t*)&qb[(r0 + lr4)     * HDn + kk + 8 + 2 * lc4];
            qa[k16][3] = *(const uint32_t*)&qb[(r0 + lr4 + 8) * HDn + kk + 8 + 2 * lc4];
        }
    }

    float O[24][4];
#pragma unroll
    for (int nt = 0; nt < 24; nt++)
#pragma unroll
        for (int q = 0; q < 4; q++) O[nt][q] = 0.f;
    float mr0 = -1e30f, mr1 = -1e30f, l0 = 0.f, l1 = 0.f;

    for (int kt = 0; kt < Nn / 64; kt++) {
        cp_wait<1>();
        __syncthreads();
        if (kt + 2 < Nn / 64) prefetch(kt + 2, (kt + 2) % 3);
        cp_commit();

        const int st = kt % 3;
        const uint32_t ks_u = (uint32_t)__cvta_generic_to_shared(ks_base + st * KVST);
        const uint32_t vs_u = (uint32_t)__cvta_generic_to_shared(vs_base + st * KVST);
        const float* kbt = kbt_base + st * 192;

        float s[8][4];
#pragma unroll
        for (int nt = 0; nt < 8; nt++)
#pragma unroll
            for (int q = 0; q < 4; q++) s[nt][q] = 0.f;
#pragma unroll
        for (int k16 = 0; k16 < 12; k16++) {
            const int kk = k16 * 16;
            uint32_t bf[8][2];
#pragma unroll
            for (int p = 0; p < 4; p++) {
                const int row = p * 16 + (g8 >> 1) * 8 + l8;
                const int col = kk + (g8 & 1) * 8;
                ldsm4(bf[2 * p][0], bf[2 * p][1], bf[2 * p + 1][0], bf[2 * p + 1][1],
                      ks_u + (row * KSs + col) * 2);
            }
#pragma unroll
            for (int nt = 0; nt < 8; nt++)
                mma16h(s[nt], qa[k16][0], qa[k16][1], qa[k16][2], qa[k16][3],
                       bf[nt][0], bf[nt][1]);
        }

        float pm0 = -1e30f, pm1 = -1e30f;
#pragma unroll
        for (int nt = 0; nt < 8; nt++) {
            const int col = nt * 8 + 2 * lc4;
            const float kb0 = -0.5f * (kbt[col]     + kbt[64 + col]     + kbt[128 + col]);
            const float kb1 = -0.5f * (kbt[col + 1] + kbt[64 + col + 1] + kbt[128 + col + 1]);
            s[nt][0] += kb0; s[nt][1] += kb1;
            s[nt][2] += kb0; s[nt][3] += kb1;
            pm0 = fmaxf(pm0, fmaxf(s[nt][0], s[nt][1]));
            pm1 = fmaxf(pm1, fmaxf(s[nt][2], s[nt][3]));
        }
        pm0 = fmaxf(pm0, __shfl_xor_sync(0xffffffffu, pm0, 1));
        pm0 = fmaxf(pm0, __shfl_xor_sync(0xffffffffu, pm0, 2));
        pm1 = fmaxf(pm1, __shfl_xor_sync(0xffffffffu, pm1, 1));
        pm1 = fmaxf(pm1, __shfl_xor_sync(0xffffffffu, pm1, 2));
        const float mn0 = fmaxf(mr0, pm0), mn1 = fmaxf(mr1, pm1);
        const float cor0 = __expf(mr0 - mn0), cor1 = __expf(mr1 - mn1);
        mr0 = mn0; mr1 = mn1;

        uint32_t pa[4][4];
        float q0 = 0.f, q1 = 0.f;
#pragma unroll
        for (int j = 0; j < 4; j++) {
#pragma unroll
            for (int hh = 0; hh < 2; hh++) {
                const int nt = 2 * j + hh;
                const float e0 = __expf(s[nt][0] - mn0);
                const float e1 = __expf(s[nt][1] - mn0);
                const float e2 = __expf(s[nt][2] - mn1);
                const float e3 = __expf(s[nt][3] - mn1);
                q0 += e0 + e1; q1 += e2 + e3;
                pa[j][2 * hh]     = h2u(__floats2half2_rn(e0, e1));
                pa[j][2 * hh + 1] = h2u(__floats2half2_rn(e2, e3));
            }
        }
        q0 += __shfl_xor_sync(0xffffffffu, q0, 1);
        q0 += __shfl_xor_sync(0xffffffffu, q0, 2);
        q1 += __shfl_xor_sync(0xffffffffu, q1, 1);
        q1 += __shfl_xor_sync(0xffffffffu, q1, 2);
        l0 = l0 * cor0 + q0;
        l1 = l1 * cor1 + q1;
#pragma unroll
        for (int nt = 0; nt < 24; nt++) {
            O[nt][0] *= cor0; O[nt][1] *= cor0;
            O[nt][2] *= cor1; O[nt][3] *= cor1;
        }

#pragma unroll
        for (int j = 0; j < 4; j++) {
            const int kk = j * 16;
#pragma unroll
            for (int p = 0; p < 12; p++) {
                const int rowv = kk + (g8 & 1) * 8 + l8;
                const int colv = p * 16 + (g8 >> 1) * 8;
                uint32_t b0A, b1A, b0B, b1B;
                ldsm4t(b0A, b1A, b0B, b1B, vs_u + (rowv * KSs + colv) * 2);
                mma16h(O[2 * p],     pa[j][0], pa[j][1], pa[j][2], pa[j][3], b0A, b1A);
                mma16h(O[2 * p + 1], pa[j][0], pa[j][1], pa[j][2], pa[j][3], b0B, b1B);
            }
        }
    }

    const float i0v = 1.0f / l0, i1v = 1.0f / l1;
    const int nrow0 = qt * 128 + r0 + lr4;
    __half* y0 = y + (size_t)(b * Nn + nrow0) * Cdim + h * HDn;
    __half* y1 = y0 + 8 * Cdim;
#pragma unroll
    for (int nt = 0; nt < 24; nt++) {
        const int col = nt * 8 + 2 * lc4;
        *(__half2*)&y0[col] = __floats2half2_rn(O[nt][0] * i0v, O[nt][1] * i0v);
        *(__half2*)&y1[col] = __floats2half2_rn(O[nt][2] * i1v, O[nt][3] * i1v);
    }
}

// ---------------- fused LN2 + RBF + fc + residual -> out (R12 fp32 version) ----------
constexpr int RBF_SMEM_BYTES = (2 * CEN * Cdim + 2 * CEN) * 4;  // 123040 B

__global__ __launch_bounds__(256) void rbf_final_kernel(
    const float* __restrict__ x1, const float* __restrict__ n2w,
    const float* __restrict__ n2b, const float* __restrict__ centers,
    const float* __restrict__ beta, const float* __restrict__ fcw,
    float* __restrict__ out)
{
    extern __shared__ __align__(16) float rsm[];
    float* cs   = rsm;                       // [CEN][Cdim] centers
    float* fwT  = rsm + CEN * Cdim;          // [CEN][Cdim] fc_w transposed
    float* cn   = fwT + CEN * Cdim;          // [CEN]
    float* bt   = cn + CEN;                  // [CEN]
    const int t = threadIdx.x;
    for (int i = t; i < CEN * Cdim; i += 256) {
        cs[i] = centers[i];
        const int j = i / Cdim, c = i % Cdim;
        fwT[i] = fcw[c * CEN + j];
    }
    __syncthreads();
    if (t < CEN) {
        float s = 0.f;
        for (int k = 0; k < Cdim; k++) s += cs[t * Cdim + k] * cs[t * Cdim + k];
        cn[t] = s;
        bt[t] = beta[t];
    }
    __syncthreads();
    const int wid = t >> 5, lane = t & 31;
    const float4* w4 = (const float4*)n2w;
    const float4* b4 = (const float4*)n2b;

    for (int rr = 0; rr < 4; rr++) {
        const int row0 = blockIdx.x * 64 + wid * 8 + rr * 2;
        const float4* xr0 = (const float4*)(x1 + (size_t)row0 * Cdim);
        const float4* xr1 = (const float4*)(x1 + (size_t)(row0 + 1) * Cdim);

        float hv0[24], hv1[24];
        float a0, a1;
        {   // row0 LN
            float4 v[6];
            float s = 0.f, s2 = 0.f;
#pragma unroll
            for (int i = 0; i < 6; i++) {
                v[i] = xr0[lane + i * 32];
                s  += v[i].x + v[i].y + v[i].z + v[i].w;
                s2 += v[i].x * v[i].x + v[i].y * v[i].y + v[i].z * v[i].z + v[i].w * v[i].w;
            }
            s = warpsum32(s); s2 = warpsum32(s2);
            const float mu = s * (1.0f / Cdim);
            const float rs = rsqrtf(s2 * (1.0f / Cdim) - mu * mu + EPSv);
            float a = 0.f;
#pragma unroll
            for (int i = 0; i < 6; i++) {
                const int idx = lane + i * 32;
                const float4 wv = w4[idx], bv = b4[idx];
                hv0[4*i+0] = (v[i].x - mu) * rs * wv.x + bv.x;
                hv0[4*i+1] = (v[i].y - mu) * rs * wv.y + bv.y;
                hv0[4*i+2] = (v[i].z - mu) * rs * wv.z + bv.z;
                hv0[4*i+3] = (v[i].w - mu) * rs * wv.w + bv.w;
                a += hv0[4*i]*hv0[4*i] + hv0[4*i+1]*hv0[4*i+1]
                   + hv0[4*i+2]*hv0[4*i+2] + hv0[4*i+3]*hv0[4*i+3];
            }
            a0 = warpsum32(a);
        }
        {   // row1 LN
            float4 v[6];
            float s = 0.f, s2 = 0.f;
#pragma unroll
            for (int i = 0; i < 6; i++) {
                v[i] = xr1[lane + i * 32];
                s  += v[i].x + v[i].y + v[i].z + v[i].w;
                s2 += v[i].x * v[i].x + v[i].y * v[i].y + v[i].z * v[i].z + v[i].w * v[i].w;
            }
            s = warpsum32(s); s2 = warpsum32(s2);
            const float mu = s * (1.0f / Cdim);
            const float rs = rsqrtf(s2 * (1.0f / Cdim) - mu * mu + EPSv);
            float a = 0.f;
#pragma unroll
            for (int i = 0; i < 6; i++) {
                const int idx = lane + i * 32;
                const float4 wv = w4[idx], bv = b4[idx];
                hv1[4*i+0] = (v[i].x - mu) * rs * wv.x + bv.x;
                hv1[4*i+1] = (v[i].y - mu) * rs * wv.y + bv.y;
                hv1[4*i+2] = (v[i].z - mu) * rs * wv.z + bv.z;
                hv1[4*i+3] = (v[i].w - mu) * rs * wv.w + bv.w;
                a += hv1[4*i]*hv1[4*i] + hv1[4*i+1]*hv1[4*i+1]
                   + hv1[4*i+2]*hv1[4*i+2] + hv1[4*i+3]*hv1[4*i+3];
            }
            a1 = warpsum32(a);
        }

        float rj0[CEN], rj1[CEN];
#pragma unroll
        for (int j = 0; j < CEN; j++) {
            const float4* cj = (const float4*)(cs + j * Cdim);
            float d0 = 0.f, d1 = 0.f;
#pragma unroll
            for (int i = 0; i < 6; i++) {
                const float4 cv = cj[lane + i * 32];
                d0 += hv0[4*i]*cv.x + hv0[4*i+1]*cv.y + hv0[4*i+2]*cv.z + hv0[4*i+3]*cv.w;
                d1 += hv1[4*i]*cv.x + hv1[4*i+1]*cv.y + hv1[4*i+2]*cv.z + hv1[4*i+3]*cv.w;
            }
            d0 = warpsum32(d0); d1 = warpsum32(d1);
            rj0[j] = __expf(-bt[j] * (a0 - 2.0f * d0 + cn[j]));
            rj1[j] = __expf(-bt[j] * (a1 - 2.0f * d1 + cn[j]));
        }

        float4* o0row = (float4*)(out + (size_t)row0 * Cdim);
        float4* o1row = (float4*)(out + (size_t)(row0 + 1) * Cdim);
#pragma unroll
        for (int i = 0; i < 6; i++) {
            const int idx = lane + i * 32;
            float4 o0 = xr0[idx];
            float4 o1 = xr1[idx];
#pragma unroll
            for (int j = 0; j < CEN; j++) {
                const float4 fv = *(const float4*)&fwT[j * Cdim + 4 * idx];
                o0.x += rj0[j] * fv.x; o0.y += rj0[j] * fv.y;
                o0.z += rj0[j] * fv.z; o0.w += rj0[j] * fv.w;
                o1.x += rj1[j] * fv.x; o1.y += rj1[j] * fv.y;
                o1.z += rj1[j] * fv.z; o1.w += rj1[j] * fv.w;
            }
            o0row[idx] = o0;
            o1row[idx] = o1;
        }
    }
}

// ---------------- launcher ----------------
extern "C" void kernel_launch(void* const* d_in, const int* in_sizes, int n_in,
                              void* d_out, int out_size)
{
    (void)in_sizes; (void)n_in; (void)out_size;
    const float* x     = (const float*)d_in[0];
    const float* n1w   = (const float*)d_in[1];
    const float* n1b   = (const float*)d_in[2];
    const float* qkvw  = (const float*)d_in[3];
    const float* Mmat  = (const float*)d_in[4];
    const float* scale = (const float*)d_in[5];
    const float* projw = (const float*)d_in[6];
    const float* projb = (const float*)d_in[7];
    const float* n2w   = (const float*)d_in[8];
    const float* n2b   = (const float*)d_in[9];
    const float* cent  = (const float*)d_in[10];
    const float* beta  = (const float*)d_in[11];
    const float* fcw   = (const float*)d_in[12];
    float* out = (float*)d_out;

    __half *hP, *qwP, *pwP, *QgP, *KgP, *VgP, *KMP, *MhP, *yP;
    float *kbpP, *x1P;
    cudaGetSymbolAddress((void**)&hP,   g_h);
    cudaGetSymbolAddress((void**)&qwP,  g_qkvwr);
    cudaGetSymbolAddress((void**)&pwP,  g_projwr);
    cudaGetSymbolAddress((void**)&QgP,  g_Qg);
    cudaGetSymbolAddress((void**)&KgP,  g_Kg);
    cudaGetSymbolAddress((void**)&VgP,  g_Vg);
    cudaGetSymbolAddress((void**)&KMP,  g_KM);
    cudaGetSymbolAddress((void**)&MhP,  g_Mh);
    cudaGetSymbolAddress((void**)&kbpP, g_kbp);
    cudaGetSymbolAddress((void**)&yP,   g_y);
    cudaGetSymbolAddress((void**)&x1P,  g_x1);

    constexpr int GS128 = 3 * (128 + 128) * 64 * 2;   // 98304 B
    constexpr int GS64  = 3 * (128 + 64) * 64 * 2;    // 73728 B
    cudaFuncSetAttribute(gemm_h<128, 1>, cudaFuncAttributeMaxDynamicSharedMemorySize, GS128);
    cudaFuncSetAttribute(gemm_h<128, 2>, cudaFuncAttributeMaxDynamicSharedMemorySize, GS128);
    cudaFuncSetAttribute(gemm_h<64, 3>,  cudaFuncAttributeMaxDynamicSharedMemorySize, GS64);
    cudaFuncSetAttribute(attn_tc_kernel, cudaFuncAttributeMaxDynamicSharedMemorySize, ATT_SMEM);
    cudaFuncSetAttribute(rbf_final_kernel, cudaFuncAttributeMaxDynamicSharedMemorySize, RBF_SMEM_BYTES);

    // streams/events for prep overlap (created once; reused across calls)
    static cudaStream_t sA = nullptr, sB = nullptr;
    static cudaEvent_t  eF = nullptr, eA = nullptr, eB = nullptr;
    if (!sA) {
        cudaStreamCreateWithFlags(&sA, cudaStreamNonBlocking);
        cudaStreamCreateWithFlags(&sB, cudaStreamNonBlocking);
        cudaEventCreateWithFlags(&eF, cudaEventDisableTiming);
        cudaEventCreateWithFlags(&eA, cudaEventDisableTiming);
        cudaEventCreateWithFlags(&eB, cudaEventDisableTiming);
    }

    // fork prep work onto side streams
    cudaEventRecord(eF, 0);
    cudaStreamWaitEvent(sA, eF, 0);
    cudaStreamWaitEvent(sB, eF, 0);
    half_copy4_kernel<<<512, 256, 0, sA>>>((const float4*)qkvw, qwP, 3 * Cdim * Cdim / 4);
    cudaEventRecord(eA, sA);
    half_copy4_kernel<<<256, 256, 0, sB>>>((const float4*)projw, pwP, Cdim * Cdim / 4);
    scale_m_kernel<<<(HDn * HDn + 255) / 256, 256, 0, sB>>>(Mmat, scale, MhP);
    cudaEventRecord(eB, sB);

    // 1) LN1 (half out) — overlaps the weight conversions
    ln1_kernel<<<Sn / 8, 256>>>(x, n1w, n1b, hP);
    // join qkv weights
    cudaStreamWaitEvent(0, eA, 0);
    // 2) qkv GEMM fused with gather -> Qg/Kg/Vg (half)
    gemm_h<128, 1><<<dim3(3 * Cdim / 128, Sn / 128), 256, GS128>>>(
        hP, qwP, QgP, KgP, VgP, Sn, 3 * Cdim, Cdim, nullptr, nullptr, nullptr);
    // join Mh (+proj weights, conservative)
    cudaStreamWaitEvent(0, eB, 0);
    // 3) KM2 = K @ (2*scale*M)^T with fused kbias partials
    gemm_h<64, 3><<<dim3(HDn / 64, BHn * Nn / 128), 256, GS64>>>(
        KgP, MhP, KMP, nullptr, nullptr, BHn * Nn, HDn, HDn, nullptr, nullptr, kbpP);
    // 4) fp16 flash attention (q . KM2 - 0.5*sum(kbp)) -> y (half)
    attn_tc_kernel<<<dim3(BHn, Nn / 128), 256, ATT_SMEM>>>(QgP, KMP, VgP, kbpP, yP);
    // 5) x1 = x + y @ proj_w^T + proj_b (fp32 out)
    gemm_h<128, 2><<<dim3(Cdim / 128, Sn / 128), 256, GS128>>>(
        yP, pwP, x1P, nullptr, nullptr, Sn, Cdim, Cdim, projb, x, nullptr);
    // 6) fused LN2 + RBF + fc + residual -> out
    rbf_final_kernel<<<Sn / 64, 256, RBF_SMEM_BYTES>>>(x1P, n2w, n2b, cent, beta, fcw, out);
}

// round 15
// speedup vs baseline: 1.0269x; 1.0132x over previous
#include <cuda_runtime.h>
#include <cuda_fp16.h>
#include <cstdint>

// ---------------- problem constants ----------------
constexpr int Cdim = 768;
constexpr int Bn   = 8;
constexpr int Nn   = 1024;
constexpr int HDn  = 192;            // head dim
constexpr int Sn   = Bn * Nn;        // 8192 rows
constexpr int BHn  = Bn * 4;         // 32
constexpr int CEN  = 20;
constexpr float EPSv = 1e-5f;

// ---------------- scratch (device globals; no allocation allowed) ----------------
__device__ __half g_h     [Sn * Cdim];
__device__ __half g_qkvwr [3 * Cdim * Cdim];
__device__ __half g_projwr[Cdim * Cdim];
__device__ __half g_Qg  [BHn * Nn * HDn];
__device__ __half g_Kg  [BHn * Nn * HDn];
__device__ __half g_Vg  [BHn * Nn * HDn];
__device__ __half g_KM  [BHn * Nn * HDn];   // KM2 = K @ (2*scale*M)^T
__device__ __half g_Mh  [HDn * HDn];        // 2*scale*M (half)
__device__ float  g_kbp [3 * BHn * Nn];     // kbias partials (one per N-block)
__device__ float  g_kb  [BHn * Nn];
__device__ __half g_y   [Sn * Cdim];
__device__ float  g_x1  [Sn * Cdim];

// ---------------- helpers ----------------
__device__ __forceinline__ float warpsum32(float v) {
#pragma unroll
    for (int o = 16; o >= 1; o >>= 1) v += __shfl_xor_sync(0xffffffffu, v, o);
    return v;
}
__device__ __forceinline__ uint32_t h2u(__half2 h) {
    return *reinterpret_cast<uint32_t*>(&h);
}
__device__ __forceinline__ void mma16h(float* c,
    uint32_t a0, uint32_t a1, uint32_t a2, uint32_t a3, uint32_t b0, uint32_t b1)
{
    asm volatile("mma.sync.aligned.m16n8k16.row.col.f32.f16.f16.f32 "
        "{%0,%1,%2,%3}, {%4,%5,%6,%7}, {%8,%9}, {%0,%1,%2,%3};"
        : "+f"(c[0]), "+f"(c[1]), "+f"(c[2]), "+f"(c[3])
        : "r"(a0), "r"(a1), "r"(a2), "r"(a3), "r"(b0), "r"(b1));
}
__device__ __forceinline__ void ldsm4(uint32_t& r0, uint32_t& r1, uint32_t& r2, uint32_t& r3,
                                      uint32_t addr)
{
    asm volatile("ldmatrix.sync.aligned.m8n8.x4.shared.b16 {%0,%1,%2,%3}, [%4];"
        : "=r"(r0), "=r"(r1), "=r"(r2), "=r"(r3) : "r"(addr));
}
__device__ __forceinline__ void ldsm4t(uint32_t& r0, uint32_t& r1, uint32_t& r2, uint32_t& r3,
                                       uint32_t addr)
{
    asm volatile("ldmatrix.sync.aligned.m8n8.x4.trans.shared.b16 {%0,%1,%2,%3}, [%4];"
        : "=r"(r0), "=r"(r1), "=r"(r2), "=r"(r3) : "r"(addr));
}
__device__ __forceinline__ void cp_async16(void* smem, const void* gmem) {
    uint32_t s = (uint32_t)__cvta_generic_to_shared(smem);
    asm volatile("cp.async.cg.shared.global [%0], [%1], 16;\n" :: "r"(s), "l"(gmem));
}
__device__ __forceinline__ void cp_commit() {
    asm volatile("cp.async.commit_group;\n");
}
template<int N>
__device__ __forceinline__ void cp_wait() {
    asm volatile("cp.async.wait_group %0;\n" :: "n"(N));
}

// ---------------- LayerNorm (LN1): warp per row, half output ----------------
__global__ __launch_bounds__(256) void ln1_kernel(
    const float* __restrict__ x, const float* __restrict__ w,
    const float* __restrict__ b, __half* __restrict__ out)
{
    const int row  = blockIdx.x * 8 + (threadIdx.x >> 5);
    const int lane = threadIdx.x & 31;
    const float4* xr = (const float4*)(x + (size_t)row * Cdim);
    float4 v[6];
    float s = 0.f, s2 = 0.f;
#pragma unroll
    for (int i = 0; i < 6; i++) {
        v[i] = xr[lane + i * 32];
        s  += v[i].x + v[i].y + v[i].z + v[i].w;
        s2 += v[i].x * v[i].x + v[i].y * v[i].y + v[i].z * v[i].z + v[i].w * v[i].w;
    }
    s = warpsum32(s); s2 = warpsum32(s2);
    const float mu  = s * (1.0f / Cdim);
    const float var = s2 * (1.0f / Cdim) - mu * mu;
    const float rs  = rsqrtf(var + EPSv);
    const float4* w4 = (const float4*)w;
    const float4* b4 = (const float4*)b;
#pragma unroll
    for (int i = 0; i < 6; i++) {
        const int idx = lane + i * 32;
        const float4 wv = w4[idx], bv = b4[idx];
        __half* orow = out + (size_t)row * Cdim + 4 * idx;
        *(__half2*)&orow[0] = __floats2half2_rn((v[i].x - mu) * rs * wv.x + bv.x,
                                                (v[i].y - mu) * rs * wv.y + bv.y);
        *(__half2*)&orow[2] = __floats2half2_rn((v[i].z - mu) * rs * wv.z + bv.z,
                                                (v[i].w - mu) * rs * wv.w + bv.w);
    }
}

// ---------------- f32 -> f16 copy (vectorized) ----------------
__global__ __launch_bounds__(256) void half_copy4_kernel(
    const float4* __restrict__ src, __half* __restrict__ dst, int n4)
{
    for (int i = blockIdx.x * 256 + threadIdx.x; i < n4; i += gridDim.x * 256) {
        const float4 v = src[i];
        *(__half2*)&dst[4 * i]     = __floats2half2_rn(v.x, v.y);
        *(__half2*)&dst[4 * i + 2] = __floats2half2_rn(v.z, v.w);
    }
}

// ---------------- Mh = 2*scale*M (half, same layout) ----------------
__global__ __launch_bounds__(256) void scale_m_kernel(
    const float* __restrict__ M, const float* __restrict__ scale_p,
    __half* __restrict__ Mh)
{
    const int i = blockIdx.x * 256 + threadIdx.x;
    if (i >= HDn * HDn) return;
    Mh[i] = __float2half(2.0f * scale_p[0] * M[i]);
}

// ---------------- 3-stage pipelined fp16 NT GEMM: C = A[M,K] * B[N,K]^T ----------------
// MODE 0: half store. MODE 1: qkv scatter -> Q/K/V half [BH][N][HD]. MODE 2: fp32 +bias+resid.
// MODE 3: half store + kbias partials kbp[bx*Md + row] = sum_n A[row,n]*acc[row,n].
template<int BN, int MODE>
__global__ __launch_bounds__(256) void gemm_h(
    const __half* __restrict__ A, const __half* __restrict__ B, void* __restrict__ Cv,
    __half* __restrict__ C2, __half* __restrict__ C3,
    int Md, int Nd, int Kd,
    const float* __restrict__ bias, const float* __restrict__ resid,
    float* __restrict__ kbp)
{
    constexpr int BM = 128, BK = 64;
    constexpr int WM = (BN == 128) ? 2 : 4;
    constexpr int WN = 8 / WM;
    constexpr int WTM = BM / WM, WTN = BN / WN;
    constexpr int MT = WTM / 16, NT = WTN / 8;
    constexpr int ASTG = BM * BK;
    constexpr int BSTG = BN * BK;

    extern __shared__ __align__(16) __half smh[];
    __half* As = smh;                 // 3 stages
    __half* Bs = smh + 3 * ASTG;      // 3 stages

    const int t = threadIdx.x;
    const int wid = t >> 5, lane = t & 31;
    const int wm = wid % WM, wn = wid / WM;
    const int lr4 = lane >> 2, lc4 = lane & 3;
    const int g8 = lane >> 3, l8 = lane & 7;
    const int m0 = blockIdx.y * BM, n0 = blockIdx.x * BN;

    const __half* Ab = A + (size_t)m0 * Kd;
    const __half* Bb = B + (size_t)n0 * Kd;

    auto prefetch = [&](int kt, int st) {
        const __half* Ag = Ab + kt * BK;
        const __half* Bg = Bb + kt * BK;
#pragma unroll
        for (int i = 0; i < BM / 32; i++) {
            const int ch = t + i * 256;
            const int r = ch >> 3, c = ch & 7;
            cp_async16(&As[st * ASTG + (r * 8 + (c ^ (r & 7))) * 8], Ag + (size_t)r * Kd + c * 8);
        }
#pragma unroll
        for (int i = 0; i < BN / 32; i++) {
            const int ch = t + i * 256;
            const int r = ch >> 3, c = ch & 7;
            cp_async16(&Bs[st * BSTG + (r * 8 + (c ^ (r & 7))) * 8], Bg + (size_t)r * Kd + c * 8);
        }
    };

    float acc[MT][NT][4];
#pragma unroll
    for (int i = 0; i < MT; i++)
#pragma unroll
        for (int j = 0; j < NT; j++)
#pragma unroll
            for (int q = 0; q < 4; q++) acc[i][j][q] = 0.f;

    const int nK = Kd / BK;
    prefetch(0, 0); cp_commit();
    prefetch(1, 1); cp_commit();

    for (int kt = 0; kt < nK; kt++) {
        cp_wait<1>();
        __syncthreads();
        if (kt + 2 < nK) prefetch(kt + 2, (kt + 2) % 3);
        cp_commit();

        const int st = kt % 3;
        const uint32_t Au = (uint32_t)__cvta_generic_to_shared(As + st * ASTG);
        const uint32_t Bu = (uint32_t)__cvta_generic_to_shared(Bs + st * BSTG);

#pragma unroll
        for (int k16 = 0; k16 < BK / 16; k16++) {
            uint32_t bf[NT][2];
#pragma unroll
            for (int p = 0; p < NT / 2; p++) {
                const int row = wn * WTN + p * 16 + (g8 >> 1) * 8 + l8;
                const int ch  = (2 * k16 + (g8 & 1)) ^ l8;
                ldsm4(bf[2 * p][0], bf[2 * p][1], bf[2 * p + 1][0], bf[2 * p + 1][1],
                      Bu + (row * 8 + ch) * 16);
            }
#pragma unroll
            for (int mt = 0; mt < MT; mt++) {
                const int rowA = wm * WTM + mt * 16 + (g8 & 1) * 8 + l8;
                const int chA  = (2 * k16 + (g8 >> 1)) ^ l8;
                uint32_t a0, a1, a2, a3;
                ldsm4(a0, a1, a2, a3, Au + (rowA * 8 + chA) * 16);
#pragma unroll
                for (int nt = 0; nt < NT; nt++)
                    mma16h(acc[mt][nt], a0, a1, a2, a3, bf[nt][0], bf[nt][1]);
            }
        }
    }

    float part[MT][2];
    if (MODE == 3) {
#pragma unroll
        for (int mt = 0; mt < MT; mt++) { part[mt][0] = 0.f; part[mt][1] = 0.f; }
    }

#pragma unroll
    for (int mt = 0; mt < MT; mt++) {
        const int mbase = m0 + wm * WTM + mt * 16 + lr4;
#pragma unroll
        for (int nt = 0; nt < NT; nt++) {
            const int n = n0 + wn * WTN + nt * 8 + 2 * lc4;
            if (MODE == 0 || MODE == 3) {
                __half* C = (__half*)Cv;
                *(__half2*)&C[(size_t)mbase * Nd + n] =
                    __floats2half2_rn(acc[mt][nt][0], acc[mt][nt][1]);
                *(__half2*)&C[(size_t)(mbase + 8) * Nd + n] =
                    __floats2half2_rn(acc[mt][nt][2], acc[mt][nt][3]);
                if (MODE == 3) {
                    const float2 k0 = __half22float2(*(const __half2*)&A[(size_t)mbase * Kd + n]);
                    const float2 k1 = __half22float2(*(const __half2*)&A[(size_t)(mbase + 8) * Kd + n]);
                    part[mt][0] += k0.x * acc[mt][nt][0] + k0.y * acc[mt][nt][1];
                    part[mt][1] += k1.x * acc[mt][nt][2] + k1.y * acc[mt][nt][3];
                }
            } else if (MODE == 1) {
                const int which = n / Cdim;
                const int rem = n % Cdim;
                const int h = rem / HDn, d = rem % HDn;
                __half* dst = (which == 0) ? (__half*)Cv : (which == 1) ? C2 : C3;
#pragma unroll
                for (int rr = 0; rr < 2; rr++) {
                    const int m = mbase + rr * 8;
                    const int b = m >> 10, nr = m & 1023;
                    const size_t di = ((size_t)((b << 2) + h) * Nn + nr) * HDn + d;
                    *(__half2*)&dst[di] =
                        __floats2half2_rn(acc[mt][nt][rr * 2], acc[mt][nt][rr * 2 + 1]);
                }
            } else {
                float* C = (float*)Cv;
                const float b0 = bias[n], b1 = bias[n + 1];
                const size_t i0 = (size_t)mbase * Nd + n;
                const size_t i1 = (size_t)(mbase + 8) * Nd + n;
                *(float2*)&C[i0] = make_float2(acc[mt][nt][0] + b0 + resid[i0],
                                               acc[mt][nt][1] + b1 + resid[i0 + 1]);
                *(float2*)&C[i1] = make_float2(acc[mt][nt][2] + b0 + resid[i1],
                                               acc[mt][nt][3] + b1 + resid[i1 + 1]);
            }
        }
    }

    if (MODE == 3) {
        float pr[MT][2];
#pragma unroll
        for (int mt = 0; mt < MT; mt++)
#pragma unroll
            for (int sr = 0; sr < 2; sr++) {
                float p = part[mt][sr];
                p += __shfl_xor_sync(0xffffffffu, p, 1);
                p += __shfl_xor_sync(0xffffffffu, p, 2);
                pr[mt][sr] = p;
            }
        __syncthreads();
        float* sred = (float*)smh;
        if (wn == 0 && lc4 == 0) {
#pragma unroll
            for (int mt = 0; mt < MT; mt++)
#pragma unroll
                for (int sr = 0; sr < 2; sr++)
                    sred[wm * WTM + mt * 16 + sr * 8 + lr4] = pr[mt][sr];
        }
        __syncthreads();
        if (wn == 1 && lc4 == 0) {
#pragma unroll
            for (int mt = 0; mt < MT; mt++)
#pragma unroll
                for (int sr = 0; sr < 2; sr++) {
                    const int rl = wm * WTM + mt * 16 + sr * 8 + lr4;
                    kbp[(size_t)blockIdx.x * Md + m0 + rl] = sred[rl] + pr[mt][sr];
                }
        }
    }
}

// ---------------- kb[r] = -0.5 * (kbp[0][r] + kbp[1][r] + kbp[2][r]) ----------------
__global__ __launch_bounds__(256) void kb_reduce_kernel(
    const float* __restrict__ kbp, float* __restrict__ kb)
{
    const int r = blockIdx.x * 256 + threadIdx.x;
    if (r >= BHn * Nn) return;
    kb[r] = -0.5f * (kbp[r] + kbp[BHn * Nn + r] + kbp[2 * BHn * Nn + r]);
}

// ---------------- fp16 flash attention (3-stage): S = q . KM2 + kb ----------------
constexpr int KSs = 200;        // K/V smem stride (halfs)
constexpr int KVST = 64 * KSs;  // halfs per stage
constexpr int ATT_SMEM = 3 * 2 * KVST * 2 + 3 * 64 * 4;   // 154368 B

__global__ __launch_bounds__(256, 1) void attn_tc_kernel(
    const __half* __restrict__ Qg, const __half* __restrict__ KM,
    const __half* __restrict__ Vg, const float* __restrict__ kbias,
    __half* __restrict__ y)
{
    extern __shared__ __align__(16) __half smha[];
    __half* ks_base = smha;                       // 3 stages (KM2 tiles)
    __half* vs_base = smha + 3 * KVST;            // 3 stages
    float* kbt_base = (float*)(smha + 6 * KVST);  // 3 x 64

    const int bh = blockIdx.x, qt = blockIdx.y;   // qt: 128-row tile
    const int b = bh >> 2, h = bh & 3;
    const int t = threadIdx.x;
    const int wid = t >> 5, lane = t & 31;
    const int lr4 = lane >> 2, lc4 = lane & 3;
    const int g8 = lane >> 3, l8 = lane & 7;
    const int r0 = wid * 16;

    auto prefetch = [&](int kt, int st) {
        const __half* kg = KM + ((size_t)bh * Nn + kt * 64) * HDn;
        const __half* vg = Vg + ((size_t)bh * Nn + kt * 64) * HDn;
        __half* ksb = ks_base + st * KVST;
        __half* vsb = vs_base + st * KVST;
#pragma unroll
        for (int i = 0; i < 6; i++) {
            const int ch = t + i * 256;
            const int r = ch / 24, c = ch % 24;
            cp_async16(&ksb[r * KSs + c * 8], kg + r * HDn + c * 8);
            cp_async16(&vsb[r * KSs + c * 8], vg + r * HDn + c * 8);
        }
        if (t < 16) cp_async16(&kbt_base[st * 64 + t * 4],
                               kbias + (size_t)bh * Nn + kt * 64 + t * 4);
    };

    prefetch(0, 0); cp_commit();
    prefetch(1, 1); cp_commit();

    uint32_t qa[12][4];
    {
        const __half* qb = Qg + ((size_t)bh * Nn + qt * 128) * HDn;
#pragma unroll
        for (int k16 = 0; k16 < 12; k16++) {
            const int kk = k16 * 16;
            qa[k16][0] = *(const uint32_t*)&qb[(r0 + lr4)     * HDn + kk + 2 * lc4];
            qa[k16][1] = *(const uint32_t*)&qb[(r0 + lr4 + 8) * HDn + kk + 2 * lc4];
            qa[k16][2] = *(const uint32_t*)&qb[(r0 + lr4)     * HDn + kk + 8 + 2 * lc4];
            qa[k16][3] = *(const uint32_t*)&qb[(r0 + lr4 + 8) * HDn + kk + 8 + 2 * lc4];
        }
    }

    float O[24][4];
#pragma unroll
    for (int nt = 0; nt < 24; nt++)
#pragma unroll
        for (int q = 0; q < 4; q++) O[nt][q] = 0.f;
    float mr0 = -1e30f, mr1 = -1e30f, l0 = 0.f, l1 = 0.f;

    for (int kt = 0; kt < Nn / 64; kt++) {
        cp_wait<1>();
        __syncthreads();
        if (kt + 2 < Nn / 64) prefetch(kt + 2, (kt + 2) % 3);
        cp_commit();

        const int st = kt % 3;
        const uint32_t ks_u = (uint32_t)__cvta_generic_to_shared(ks_base + st * KVST);
        const uint32_t vs_u = (uint32_t)__cvta_generic_to_shared(vs_base + st * KVST);
        const float* kbt = kbt_base + st * 64;

        float s[8][4];
#pragma unroll
        for (int nt = 0; nt < 8; nt++)
#pragma unroll
            for (int q = 0; q < 4; q++) s[nt][q] = 0.f;
#pragma unroll
        for (int k16 = 0; k16 < 12; k16++) {
            const int kk = k16 * 16;
            uint32_t bf[8][2];
#pragma unroll
            for (int p = 0; p < 4; p++) {
                const int row = p * 16 + (g8 >> 1) * 8 + l8;
                const int col = kk + (g8 & 1) * 8;
                ldsm4(bf[2 * p][0], bf[2 * p][1], bf[2 * p + 1][0], bf[2 * p + 1][1],
                      ks_u + (row * KSs + col) * 2);
            }
#pragma unroll
            for (int nt = 0; nt < 8; nt++)
                mma16h(s[nt], qa[k16][0], qa[k16][1], qa[k16][2], qa[k16][3],
                       bf[nt][0], bf[nt][1]);
        }

        float pm0 = -1e30f, pm1 = -1e30f;
#pragma unroll
        for (int nt = 0; nt < 8; nt++) {
            const int col = nt * 8 + 2 * lc4;
            const float kb0 = kbt[col], kb1 = kbt[col + 1];
            s[nt][0] += kb0; s[nt][1] += kb1;
            s[nt][2] += kb0; s[nt][3] += kb1;
            pm0 = fmaxf(pm0, fmaxf(s[nt][0], s[nt][1]));
            pm1 = fmaxf(pm1, fmaxf(s[nt][2], s[nt][3]));
        }
        pm0 = fmaxf(pm0, __shfl_xor_sync(0xffffffffu, pm0, 1));
        pm0 = fmaxf(pm0, __shfl_xor_sync(0xffffffffu, pm0, 2));
        pm1 = fmaxf(pm1, __shfl_xor_sync(0xffffffffu, pm1, 1));
        pm1 = fmaxf(pm1, __shfl_xor_sync(0xffffffffu, pm1, 2));
        const float mn0 = fmaxf(mr0, pm0), mn1 = fmaxf(mr1, pm1);
        const float cor0 = __expf(mr0 - mn0), cor1 = __expf(mr1 - mn1);
        mr0 = mn0; mr1 = mn1;

        uint32_t pa[4][4];
        float q0 = 0.f, q1 = 0.f;
#pragma unroll
        for (int j = 0; j < 4; j++) {
#pragma unroll
            for (int hh = 0; hh < 2; hh++) {
                const int nt = 2 * j + hh;
                const float e0 = __expf(s[nt][0] - mn0);
                const float e1 = __expf(s[nt][1] - mn0);
                const float e2 = __expf(s[nt][2] - mn1);
                const float e3 = __expf(s[nt][3] - mn1);
                q0 += e0 + e1; q1 += e2 + e3;
                pa[j][2 * hh]     = h2u(__floats2half2_rn(e0, e1));
                pa[j][2 * hh + 1] = h2u(__floats2half2_rn(e2, e3));
            }
        }
        q0 += __shfl_xor_sync(0xffffffffu, q0, 1);
        q0 += __shfl_xor_sync(0xffffffffu, q0, 2);
        q1 += __shfl_xor_sync(0xffffffffu, q1, 1);
        q1 += __shfl_xor_sync(0xffffffffu, q1, 2);
        l0 = l0 * cor0 + q0;
        l1 = l1 * cor1 + q1;
#pragma unroll
        for (int nt = 0; nt < 24; nt++) {
            O[nt][0] *= cor0; O[nt][1] *= cor0;
            O[nt][2] *= cor1; O[nt][3] *= cor1;
        }

#pragma unroll
        for (int j = 0; j < 4; j++) {
            const int kk = j * 16;
#pragma unroll
            for (int p = 0; p < 12; p++) {
                const int rowv = kk + (g8 & 1) * 8 + l8;
                const int colv = p * 16 + (g8 >> 1) * 8;
                uint32_t b0A, b1A, b0B, b1B;
                ldsm4t(b0A, b1A, b0B, b1B, vs_u + (rowv * KSs + colv) * 2);
                mma16h(O[2 * p],     pa[j][0], pa[j][1], pa[j][2], pa[j][3], b0A, b1A);
                mma16h(O[2 * p + 1], pa[j][0], pa[j][1], pa[j][2], pa[j][3], b0B, b1B);
            }
        }
    }

    const float i0v = 1.0f / l0, i1v = 1.0f / l1;
    const int nrow0 = qt * 128 + r0 + lr4;
    __half* y0 = y + (size_t)(b * Nn + nrow0) * Cdim + h * HDn;
    __half* y1 = y0 + 8 * Cdim;
#pragma unroll
    for (int nt = 0; nt < 24; nt++) {
        const int col = nt * 8 + 2 * lc4;
        *(__half2*)&y0[col] = __floats2half2_rn(O[nt][0] * i0v, O[nt][1] * i0v);
        *(__half2*)&y1[col] = __floats2half2_rn(O[nt][2] * i1v, O[nt][3] * i1v);
    }
}

// ---------------- fused LN2 + RBF + fc + residual -> out (2 rows / warp-iter) --------
constexpr int RBF_SMEM_BYTES = (2 * CEN * Cdim + 2 * CEN) * 4;  // 123040 B

__global__ __launch_bounds__(256) void rbf_final_kernel(
    const float* __restrict__ x1, const float* __restrict__ n2w,
    const float* __restrict__ n2b, const float* __restrict__ centers,
    const float* __restrict__ beta, const float* __restrict__ fcw,
    float* __restrict__ out)
{
    extern __shared__ __align__(16) float rsm[];
    float* cs   = rsm;                       // [CEN][Cdim] centers
    float* fwT  = rsm + CEN * Cdim;          // [CEN][Cdim] fc_w transposed
    float* cn   = fwT + CEN * Cdim;          // [CEN]
    float* bt   = cn + CEN;                  // [CEN]
    const int t = threadIdx.x;
    for (int i = t; i < CEN * Cdim; i += 256) {
        cs[i] = centers[i];
        const int j = i / Cdim, c = i % Cdim;
        fwT[i] = fcw[c * CEN + j];
    }
    __syncthreads();
    if (t < CEN) {
        float s = 0.f;
        for (int k = 0; k < Cdim; k++) s += cs[t * Cdim + k] * cs[t * Cdim + k];
        cn[t] = s;
        bt[t] = beta[t];
    }
    __syncthreads();
    const int wid = t >> 5, lane = t & 31;
    const float4* w4 = (const float4*)n2w;
    const float4* b4 = (const float4*)n2b;

    for (int rr = 0; rr < 4; rr++) {
        const int row0 = blockIdx.x * 64 + wid * 8 + rr * 2;
        const float4* xr0 = (const float4*)(x1 + (size_t)row0 * Cdim);
        const float4* xr1 = (const float4*)(x1 + (size_t)(row0 + 1) * Cdim);

        float hv0[24], hv1[24];
        float a0, a1;
        {   // row0 LN
            float4 v[6];
            float s = 0.f, s2 = 0.f;
#pragma unroll
            for (int i = 0; i < 6; i++) {
                v[i] = xr0[lane + i * 32];
                s  += v[i].x + v[i].y + v[i].z + v[i].w;
                s2 += v[i].x * v[i].x + v[i].y * v[i].y + v[i].z * v[i].z + v[i].w * v[i].w;
            }
            s = warpsum32(s); s2 = warpsum32(s2);
            const float mu = s * (1.0f / Cdim);
            const float rs = rsqrtf(s2 * (1.0f / Cdim) - mu * mu + EPSv);
            float a = 0.f;
#pragma unroll
            for (int i = 0; i < 6; i++) {
                const int idx = lane + i * 32;
                const float4 wv = w4[idx], bv = b4[idx];
                hv0[4*i+0] = (v[i].x - mu) * rs * wv.x + bv.x;
                hv0[4*i+1] = (v[i].y - mu) * rs * wv.y + bv.y;
                hv0[4*i+2] = (v[i].z - mu) * rs * wv.z + bv.z;
                hv0[4*i+3] = (v[i].w - mu) * rs * wv.w + bv.w;
                a += hv0[4*i]*hv0[4*i] + hv0[4*i+1]*hv0[4*i+1]
                   + hv0[4*i+2]*hv0[4*i+2] + hv0[4*i+3]*hv0[4*i+3];
            }
            a0 = warpsum32(a);
        }
        {   // row1 LN
            float4 v[6];
            float s = 0.f, s2 = 0.f;
#pragma unroll
            for (int i = 0; i < 6; i++) {
                v[i] = xr1[lane + i * 32];
                s  += v[i].x + v[i].y + v[i].z + v[i].w;
                s2 += v[i].x * v[i].x + v[i].y * v[i].y + v[i].z * v[i].z + v[i].w * v[i].w;
            }
            s = warpsum32(s); s2 = warpsum32(s2);
            const float mu = s * (1.0f / Cdim);
            const float rs = rsqrtf(s2 * (1.0f / Cdim) - mu * mu + EPSv);
            float a = 0.f;
#pragma unroll
            for (int i = 0; i < 6; i++) {
                const int idx = lane + i * 32;
                const float4 wv = w4[idx], bv = b4[idx];
                hv1[4*i+0] = (v[i].x - mu) * rs * wv.x + bv.x;
                hv1[4*i+1] = (v[i].y - mu) * rs * wv.y + bv.y;
                hv1[4*i+2] = (v[i].z - mu) * rs * wv.z + bv.z;
                hv1[4*i+3] = (v[i].w - mu) * rs * wv.w + bv.w;
                a += hv1[4*i]*hv1[4*i] + hv1[4*i+1]*hv1[4*i+1]
                   + hv1[4*i+2]*hv1[4*i+2] + hv1[4*i+3]*hv1[4*i+3];
            }
            a1 = warpsum32(a);
        }

        float rj0[CEN], rj1[CEN];
#pragma unroll
        for (int j = 0; j < CEN; j++) {
            const float4* cj = (const float4*)(cs + j * Cdim);
            float d0 = 0.f, d1 = 0.f;
#pragma unroll
            for (int i = 0; i < 6; i++) {
                const float4 cv = cj[lane + i * 32];
                d0 += hv0[4*i]*cv.x + hv0[4*i+1]*cv.y + hv0[4*i+2]*cv.z + hv0[4*i+3]*cv.w;
                d1 += hv1[4*i]*cv.x + hv1[4*i+1]*cv.y + hv1[4*i+2]*cv.z + hv1[4*i+3]*cv.w;
            }
            d0 = warpsum32(d0); d1 = warpsum32(d1);
            rj0[j] = __expf(-bt[j] * (a0 - 2.0f * d0 + cn[j]));
            rj1[j] = __expf(-bt[j] * (a1 - 2.0f * d1 + cn[j]));
        }

        float4* o0row = (float4*)(out + (size_t)row0 * Cdim);
        float4* o1row = (float4*)(out + (size_t)(row0 + 1) * Cdim);
#pragma unroll
        for (int i = 0; i < 6; i++) {
            const int idx = lane + i * 32;
            float4 o0 = xr0[idx];
            float4 o1 = xr1[idx];
#pragma unroll
            for (int j = 0; j < CEN; j++) {
                const float4 fv = *(const float4*)&fwT[j * Cdim + 4 * idx];
                o0.x += rj0[j] * fv.x; o0.y += rj0[j] * fv.y;
                o0.z += rj0[j] * fv.z; o0.w += rj0[j] * fv.w;
                o1.x += rj1[j] * fv.x; o1.y += rj1[j] * fv.y;
                o1.z += rj1[j] * fv.z; o1.w += rj1[j] * fv.w;
            }
            o0row[idx] = o0;
            o1row[idx] = o1;
        }
    }
}

// ---------------- launcher ----------------
extern "C" void kernel_launch(void* const* d_in, const int* in_sizes, int n_in,
                              void* d_out, int out_size)
{
    (void)in_sizes; (void)n_in; (void)out_size;
    const float* x     = (const float*)d_in[0];
    const float* n1w   = (const float*)d_in[1];
    const float* n1b   = (const float*)d_in[2];
    const float* qkvw  = (const float*)d_in[3];
    const float* Mmat  = (const float*)d_in[4];
    const float* scale = (const float*)d_in[5];
    const float* projw = (const float*)d_in[6];
    const float* projb = (const float*)d_in[7];
    const float* n2w   = (const float*)d_in[8];
    const float* n2b   = (const float*)d_in[9];
    const float* cent  = (const float*)d_in[10];
    const float* beta  = (const float*)d_in[11];
    const float* fcw   = (const float*)d_in[12];
    float* out = (float*)d_out;

    __half *hP, *qwP, *pwP, *QgP, *KgP, *VgP, *KMP, *MhP, *yP;
    float *kbpP, *kbP, *x1P;
    cudaGetSymbolAddress((void**)&hP,   g_h);
    cudaGetSymbolAddress((void**)&qwP,  g_qkvwr);
    cudaGetSymbolAddress((void**)&pwP,  g_projwr);
    cudaGetSymbolAddress((void**)&QgP,  g_Qg);
    cudaGetSymbolAddress((void**)&KgP,  g_Kg);
    cudaGetSymbolAddress((void**)&VgP,  g_Vg);
    cudaGetSymbolAddress((void**)&KMP,  g_KM);
    cudaGetSymbolAddress((void**)&MhP,  g_Mh);
    cudaGetSymbolAddress((void**)&kbpP, g_kbp);
    cudaGetSymbolAddress((void**)&kbP,  g_kb);
    cudaGetSymbolAddress((void**)&yP,   g_y);
    cudaGetSymbolAddress((void**)&x1P,  g_x1);

    constexpr int GS128 = 3 * (128 + 128) * 64 * 2;   // 98304 B
    constexpr int GS64  = 3 * (128 + 64) * 64 * 2;    // 73728 B
    cudaFuncSetAttribute(gemm_h<128, 1>, cudaFuncAttributeMaxDynamicSharedMemorySize, GS128);
    cudaFuncSetAttribute(gemm_h<128, 2>, cudaFuncAttributeMaxDynamicSharedMemorySize, GS128);
    cudaFuncSetAttribute(gemm_h<64, 3>,  cudaFuncAttributeMaxDynamicSharedMemorySize, GS64);
    cudaFuncSetAttribute(attn_tc_kernel, cudaFuncAttributeMaxDynamicSharedMemorySize, ATT_SMEM);
    cudaFuncSetAttribute(rbf_final_kernel, cudaFuncAttributeMaxDynamicSharedMemorySize, RBF_SMEM_BYTES);

    // streams/events for prep overlap (created once; reused across calls)
    static cudaStream_t sA = nullptr, sB = nullptr;
    static cudaEvent_t  eF = nullptr, eA = nullptr, eB = nullptr;
    if (!sA) {
        cudaStreamCreateWithFlags(&sA, cudaStreamNonBlocking);
        cudaStreamCreateWithFlags(&sB, cudaStreamNonBlocking);
        cudaEventCreateWithFlags(&eF, cudaEventDisableTiming);
        cudaEventCreateWithFlags(&eA, cudaEventDisableTiming);
        cudaEventCreateWithFlags(&eB, cudaEventDisableTiming);
    }

    // fork prep work onto side streams
    cudaEventRecord(eF, 0);
    cudaStreamWaitEvent(sA, eF, 0);
    cudaStreamWaitEvent(sB, eF, 0);
    half_copy4_kernel<<<512, 256, 0, sA>>>((const float4*)qkvw, qwP, 3 * Cdim * Cdim / 4);
    cudaEventRecord(eA, sA);
    half_copy4_kernel<<<256, 256, 0, sB>>>((const float4*)projw, pwP, Cdim * Cdim / 4);
    scale_m_kernel<<<(HDn * HDn + 255) / 256, 256, 0, sB>>>(Mmat, scale, MhP);
    cudaEventRecord(eB, sB);

    // 1) LN1 (half out) — overlaps the weight conversions
    ln1_kernel<<<Sn / 8, 256>>>(x, n1w, n1b, hP);
    // join qkv weights
    cudaStreamWaitEvent(0, eA, 0);
    // 2) qkv GEMM fused with gather -> Qg/Kg/Vg (half)
    gemm_h<128, 1><<<dim3(3 * Cdim / 128, Sn / 128), 256, GS128>>>(
        hP, qwP, QgP, KgP, VgP, Sn, 3 * Cdim, Cdim, nullptr, nullptr, nullptr);
    // join Mh (+proj weights, conservative)
    cudaStreamWaitEvent(0, eB, 0);
    // 3) KM2 = K @ (2*scale*M)^T with fused kbias partials
    gemm_h<64, 3><<<dim3(HDn / 64, BHn * Nn / 128), 256, GS64>>>(
        KgP, MhP, KMP, nullptr, nullptr, BHn * Nn, HDn, HDn, nullptr, nullptr, kbpP);
    // 4) kb = -0.5 * sum(partials)
    kb_reduce_kernel<<<(BHn * Nn + 255) / 256, 256>>>(kbpP, kbP);
    // 5) fp16 flash attention (q . KM2 + kb) -> y (half)
    attn_tc_kernel<<<dim3(BHn, Nn / 128), 256, ATT_SMEM>>>(QgP, KMP, VgP, kbP, yP);
    // 6) x1 = x + y @ proj_w^T + proj_b (fp32 out)
    gemm_h<128, 2><<<dim3(Cdim / 128, Sn / 128), 256, GS128>>>(
        yP, pwP, x1P, nullptr, nullptr, Sn, Cdim, Cdim, projb, x, nullptr);
    // 7) fused LN2 + RBF + fc + residual -> out
    rbf_final_kernel<<<Sn / 64, 256, RBF_SMEM_BYTES>>>(x1P, n2w, n2b, cent, beta, fcw, out);
}

// round 16
// speedup vs baseline: 1.0292x; 1.0023x over previous
#include <cuda_runtime.h>
#include <cuda_fp16.h>
#include <cstdint>

// ---------------- problem constants ----------------
constexpr int Cdim = 768;
constexpr int Bn   = 8;
constexpr int Nn   = 1024;
constexpr int HDn  = 192;            // head dim
constexpr int Sn   = Bn * Nn;        // 8192 rows
constexpr int BHn  = Bn * 4;         // 32
constexpr int CEN  = 20;
constexpr float EPSv = 1e-5f;

// ---------------- scratch (device globals; no allocation allowed) ----------------
__device__ __half g_h     [Sn * Cdim];
__device__ __half g_qkvwr [3 * Cdim * Cdim];
__device__ __half g_projwr[Cdim * Cdim];
__device__ __half g_Qg  [BHn * Nn * HDn];
__device__ __half g_Kg  [BHn * Nn * HDn];
__device__ __half g_Vg  [BHn * Nn * HDn];
__device__ __half g_KM  [BHn * Nn * HDn];   // KM2 = K @ (2*scale*M)^T
__device__ __half g_Mh  [HDn * HDn];        // 2*scale*M (half)
__device__ float  g_kbp [3 * BHn * Nn];     // kbias partials (one per N-block)
__device__ float  g_kb  [BHn * Nn];
__device__ __half g_y   [Sn * Cdim];
__device__ float  g_x1  [Sn * Cdim];

// ---------------- helpers ----------------
__device__ __forceinline__ float warpsum32(float v) {
#pragma unroll
    for (int o = 16; o >= 1; o >>= 1) v += __shfl_xor_sync(0xffffffffu, v, o);
    return v;
}
__device__ __forceinline__ uint32_t h2u(__half2 h) {
    return *reinterpret_cast<uint32_t*>(&h);
}
__device__ __forceinline__ void mma16h(float* c,
    uint32_t a0, uint32_t a1, uint32_t a2, uint32_t a3, uint32_t b0, uint32_t b1)
{
    asm volatile("mma.sync.aligned.m16n8k16.row.col.f32.f16.f16.f32 "
        "{%0,%1,%2,%3}, {%4,%5,%6,%7}, {%8,%9}, {%0,%1,%2,%3};"
        : "+f"(c[0]), "+f"(c[1]), "+f"(c[2]), "+f"(c[3])
        : "r"(a0), "r"(a1), "r"(a2), "r"(a3), "r"(b0), "r"(b1));
}
__device__ __forceinline__ void ldsm4(uint32_t& r0, uint32_t& r1, uint32_t& r2, uint32_t& r3,
                                      uint32_t addr)
{
    asm volatile("ldmatrix.sync.aligned.m8n8.x4.shared.b16 {%0,%1,%2,%3}, [%4];"
        : "=r"(r0), "=r"(r1), "=r"(r2), "=r"(r3) : "r"(addr));
}
__device__ __forceinline__ void ldsm4t(uint32_t& r0, uint32_t& r1, uint32_t& r2, uint32_t& r3,
                                       uint32_t addr)
{
    asm volatile("ldmatrix.sync.aligned.m8n8.x4.trans.shared.b16 {%0,%1,%2,%3}, [%4];"
        : "=r"(r0), "=r"(r1), "=r"(r2), "=r"(r3) : "r"(addr));
}
__device__ __forceinline__ void cp_async16(void* smem, const void* gmem) {
    uint32_t s = (uint32_t)__cvta_generic_to_shared(smem);
    asm volatile("cp.async.cg.shared.global [%0], [%1], 16;\n" :: "r"(s), "l"(gmem));
}
__device__ __forceinline__ void cp_commit() {
    asm volatile("cp.async.commit_group;\n");
}
template<int N>
__device__ __forceinline__ void cp_wait() {
    asm volatile("cp.async.wait_group %0;\n" :: "n"(N));
}

// ---------------- LayerNorm (LN1): warp per row, half output ----------------
__global__ __launch_bounds__(256) void ln1_kernel(
    const float* __restrict__ x, const float* __restrict__ w,
    const float* __restrict__ b, __half* __restrict__ out)
{
    const int row  = blockIdx.x * 8 + (threadIdx.x >> 5);
    const int lane = threadIdx.x & 31;
    const float4* xr = (const float4*)(x + (size_t)row * Cdim);
    float4 v[6];
    float s = 0.f, s2 = 0.f;
#pragma unroll
    for (int i = 0; i < 6; i++) {
        v[i] = xr[lane + i * 32];
        s  += v[i].x + v[i].y + v[i].z + v[i].w;
        s2 += v[i].x * v[i].x + v[i].y * v[i].y + v[i].z * v[i].z + v[i].w * v[i].w;
    }
    s = warpsum32(s); s2 = warpsum32(s2);
    const float mu  = s * (1.0f / Cdim);
    const float var = s2 * (1.0f / Cdim) - mu * mu;
    const float rs  = rsqrtf(var + EPSv);
    const float4* w4 = (const float4*)w;
    const float4* b4 = (const float4*)b;
#pragma unroll
    for (int i = 0; i < 6; i++) {
        const int idx = lane + i * 32;
        const float4 wv = w4[idx], bv = b4[idx];
        __half* orow = out + (size_t)row * Cdim + 4 * idx;
        *(__half2*)&orow[0] = __floats2half2_rn((v[i].x - mu) * rs * wv.x + bv.x,
                                                (v[i].y - mu) * rs * wv.y + bv.y);
        *(__half2*)&orow[2] = __floats2half2_rn((v[i].z - mu) * rs * wv.z + bv.z,
                                                (v[i].w - mu) * rs * wv.w + bv.w);
    }
}

// ---------------- f32 -> f16 copy (vectorized) ----------------
__global__ __launch_bounds__(256) void half_copy4_kernel(
    const float4* __restrict__ src, __half* __restrict__ dst, int n4)
{
    for (int i = blockIdx.x * 256 + threadIdx.x; i < n4; i += gridDim.x * 256) {
        const float4 v = src[i];
        *(__half2*)&dst[4 * i]     = __floats2half2_rn(v.x, v.y);
        *(__half2*)&dst[4 * i + 2] = __floats2half2_rn(v.z, v.w);
    }
}

// ---------------- Mh = 2*scale*M (half, same layout) ----------------
__global__ __launch_bounds__(256) void scale_m_kernel(
    const float* __restrict__ M, const float* __restrict__ scale_p,
    __half* __restrict__ Mh)
{
    const int i = blockIdx.x * 256 + threadIdx.x;
    if (i >= HDn * HDn) return;
    Mh[i] = __float2half(2.0f * scale_p[0] * M[i]);
}

// ---------------- 3-stage pipelined fp16 NT GEMM: C = A[M,K] * B[N,K]^T ----------------
// MODE 0: half store. MODE 1: qkv scatter -> Q/K/V half [BH][N][HD]. MODE 2: fp32 +bias+resid.
// MODE 3: half store + kbias partials kbp[bx*Md + row] = sum_n A[row,n]*acc[row,n].
template<int BN, int MODE>
__global__ __launch_bounds__(256) void gemm_h(
    const __half* __restrict__ A, const __half* __restrict__ B, void* __restrict__ Cv,
    __half* __restrict__ C2, __half* __restrict__ C3,
    int Md, int Nd, int Kd,
    const float* __restrict__ bias, const float* __restrict__ resid,
    float* __restrict__ kbp)
{
    constexpr int BM = 128, BK = 64;
    constexpr int WM = (BN == 128) ? 2 : 4;
    constexpr int WN = 8 / WM;
    constexpr int WTM = BM / WM, WTN = BN / WN;
    constexpr int MT = WTM / 16, NT = WTN / 8;
    constexpr int ASTG = BM * BK;
    constexpr int BSTG = BN * BK;

    extern __shared__ __align__(16) __half smh[];
    __half* As = smh;                 // 3 stages
    __half* Bs = smh + 3 * ASTG;      // 3 stages

    const int t = threadIdx.x;
    const int wid = t >> 5, lane = t & 31;
    const int wm = wid % WM, wn = wid / WM;
    const int lr4 = lane >> 2, lc4 = lane & 3;
    const int g8 = lane >> 3, l8 = lane & 7;
    const int m0 = blockIdx.y * BM, n0 = blockIdx.x * BN;

    const __half* Ab = A + (size_t)m0 * Kd;
    const __half* Bb = B + (size_t)n0 * Kd;

    auto prefetch = [&](int kt, int st) {
        const __half* Ag = Ab + kt * BK;
        const __half* Bg = Bb + kt * BK;
#pragma unroll
        for (int i = 0; i < BM / 32; i++) {
            const int ch = t + i * 256;
            const int r = ch >> 3, c = ch & 7;
            cp_async16(&As[st * ASTG + (r * 8 + (c ^ (r & 7))) * 8], Ag + (size_t)r * Kd + c * 8);
        }
#pragma unroll
        for (int i = 0; i < BN / 32; i++) {
            const int ch = t + i * 256;
            const int r = ch >> 3, c = ch & 7;
            cp_async16(&Bs[st * BSTG + (r * 8 + (c ^ (r & 7))) * 8], Bg + (size_t)r * Kd + c * 8);
        }
    };

    float acc[MT][NT][4];
#pragma unroll
    for (int i = 0; i < MT; i++)
#pragma unroll
        for (int j = 0; j < NT; j++)
#pragma unroll
            for (int q = 0; q < 4; q++) acc[i][j][q] = 0.f;

    const int nK = Kd / BK;
    prefetch(0, 0); cp_commit();
    prefetch(1, 1); cp_commit();

    for (int kt = 0; kt < nK; kt++) {
        cp_wait<1>();
        __syncthreads();
        if (kt + 2 < nK) prefetch(kt + 2, (kt + 2) % 3);
        cp_commit();

        const int st = kt % 3;
        const uint32_t Au = (uint32_t)__cvta_generic_to_shared(As + st * ASTG);
        const uint32_t Bu = (uint32_t)__cvta_generic_to_shared(Bs + st * BSTG);

#pragma unroll
        for (int k16 = 0; k16 < BK / 16; k16++) {
            uint32_t bf[NT][2];
#pragma unroll
            for (int p = 0; p < NT / 2; p++) {
                const int row = wn * WTN + p * 16 + (g8 >> 1) * 8 + l8;
                const int ch  = (2 * k16 + (g8 & 1)) ^ l8;
                ldsm4(bf[2 * p][0], bf[2 * p][1], bf[2 * p + 1][0], bf[2 * p + 1][1],
                      Bu + (row * 8 + ch) * 16);
            }
#pragma unroll
            for (int mt = 0; mt < MT; mt++) {
                const int rowA = wm * WTM + mt * 16 + (g8 & 1) * 8 + l8;
                const int chA  = (2 * k16 + (g8 >> 1)) ^ l8;
                uint32_t a0, a1, a2, a3;
                ldsm4(a0, a1, a2, a3, Au + (rowA * 8 + chA) * 16);
#pragma unroll
                for (int nt = 0; nt < NT; nt++)
                    mma16h(acc[mt][nt], a0, a1, a2, a3, bf[nt][0], bf[nt][1]);
            }
        }
    }

    float part[MT][2];
    if (MODE == 3) {
#pragma unroll
        for (int mt = 0; mt < MT; mt++) { part[mt][0] = 0.f; part[mt][1] = 0.f; }
    }

#pragma unroll
    for (int mt = 0; mt < MT; mt++) {
        const int mbase = m0 + wm * WTM + mt * 16 + lr4;
#pragma unroll
        for (int nt = 0; nt < NT; nt++) {
            const int n = n0 + wn * WTN + nt * 8 + 2 * lc4;
            if (MODE == 0 || MODE == 3) {
                __half* C = (__half*)Cv;
                *(__half2*)&C[(size_t)mbase * Nd + n] =
                    __floats2half2_rn(acc[mt][nt][0], acc[mt][nt][1]);
                *(__half2*)&C[(size_t)(mbase + 8) * Nd + n] =
                    __floats2half2_rn(acc[mt][nt][2], acc[mt][nt][3]);
                if (MODE == 3) {
                    const float2 k0 = __half22float2(*(const __half2*)&A[(size_t)mbase * Kd + n]);
                    const float2 k1 = __half22float2(*(const __half2*)&A[(size_t)(mbase + 8) * Kd + n]);
                    part[mt][0] += k0.x * acc[mt][nt][0] + k0.y * acc[mt][nt][1];
                    part[mt][1] += k1.x * acc[mt][nt][2] + k1.y * acc[mt][nt][3];
                }
            } else if (MODE == 1) {
                const int which = n / Cdim;
                const int rem = n % Cdim;
                const int h = rem / HDn, d = rem % HDn;
                __half* dst = (which == 0) ? (__half*)Cv : (which == 1) ? C2 : C3;
#pragma unroll
                for (int rr = 0; rr < 2; rr++) {
                    const int m = mbase + rr * 8;
                    const int b = m >> 10, nr = m & 1023;
                    const size_t di = ((size_t)((b << 2) + h) * Nn + nr) * HDn + d;
                    *(__half2*)&dst[di] =
                        __floats2half2_rn(acc[mt][nt][rr * 2], acc[mt][nt][rr * 2 + 1]);
                }
            } else {
                float* C = (float*)Cv;
                const float b0 = bias[n], b1 = bias[n + 1];
                const size_t i0 = (size_t)mbase * Nd + n;
                const size_t i1 = (size_t)(mbase + 8) * Nd + n;
                *(float2*)&C[i0] = make_float2(acc[mt][nt][0] + b0 + resid[i0],
                                               acc[mt][nt][1] + b1 + resid[i0 + 1]);
                *(float2*)&C[i1] = make_float2(acc[mt][nt][2] + b0 + resid[i1],
                                               acc[mt][nt][3] + b1 + resid[i1 + 1]);
            }
        }
    }

    if (MODE == 3) {
        float pr[MT][2];
#pragma unroll
        for (int mt = 0; mt < MT; mt++)
#pragma unroll
            for (int sr = 0; sr < 2; sr++) {
                float p = part[mt][sr];
                p += __shfl_xor_sync(0xffffffffu, p, 1);
                p += __shfl_xor_sync(0xffffffffu, p, 2);
                pr[mt][sr] = p;
            }
        __syncthreads();
        float* sred = (float*)smh;
        if (wn == 0 && lc4 == 0) {
#pragma unroll
            for (int mt = 0; mt < MT; mt++)
#pragma unroll
                for (int sr = 0; sr < 2; sr++)
                    sred[wm * WTM + mt * 16 + sr * 8 + lr4] = pr[mt][sr];
        }
        __syncthreads();
        if (wn == 1 && lc4 == 0) {
#pragma unroll
            for (int mt = 0; mt < MT; mt++)
#pragma unroll
                for (int sr = 0; sr < 2; sr++) {
                    const int rl = wm * WTM + mt * 16 + sr * 8 + lr4;
                    kbp[(size_t)blockIdx.x * Md + m0 + rl] = sred[rl] + pr[mt][sr];
                }
        }
    }
}

// ---------------- kb[r] = -0.5 * (kbp[0][r] + kbp[1][r] + kbp[2][r]) ----------------
__global__ __launch_bounds__(256) void kb_reduce_kernel(
    const float* __restrict__ kbp, float* __restrict__ kb)
{
    const int r = blockIdx.x * 256 + threadIdx.x;
    if (r >= BHn * Nn) return;
    kb[r] = -0.5f * (kbp[r] + kbp[BHn * Nn + r] + kbp[2 * BHn * Nn + r]);
}

// ---------------- fp16 flash attention, 128-key softmax cadence ----------------
// 4-stage 64-key ring processed in pairs: S over 128 keys, ONE softmax pass,
// then P@V against both V stages. Halves O-rescale/bookkeeping passes.
constexpr int KSs = 200;        // K/V smem stride (halfs)
constexpr int KVST = 64 * KSs;  // halfs per stage
constexpr int ATT_SMEM = 4 * 2 * KVST * 2 + 4 * 64 * 4;   // 205824 B

__global__ __launch_bounds__(256, 1) void attn_tc_kernel(
    const __half* __restrict__ Qg, const __half* __restrict__ KM,
    const __half* __restrict__ Vg, const float* __restrict__ kbias,
    __half* __restrict__ y)
{
    extern __shared__ __align__(16) __half smha[];
    __half* ks_base = smha;                       // 4 stages (KM2 tiles)
    __half* vs_base = smha + 4 * KVST;            // 4 stages
    float* kbt_base = (float*)(smha + 8 * KVST);  // 4 x 64

    const int bh = blockIdx.x, qt = blockIdx.y;   // qt: 128-row tile
    const int b = bh >> 2, h = bh & 3;
    const int t = threadIdx.x;
    const int wid = t >> 5, lane = t & 31;
    const int lr4 = lane >> 2, lc4 = lane & 3;
    const int g8 = lane >> 3, l8 = lane & 7;
    const int r0 = wid * 16;

    auto prefetch = [&](int kt, int st) {
        const __half* kg = KM + ((size_t)bh * Nn + kt * 64) * HDn;
        const __half* vg = Vg + ((size_t)bh * Nn + kt * 64) * HDn;
        __half* ksb = ks_base + st * KVST;
        __half* vsb = vs_base + st * KVST;
#pragma unroll
        for (int i = 0; i < 6; i++) {
            const int ch = t + i * 256;
            const int r = ch / 24, c = ch % 24;
            cp_async16(&ksb[r * KSs + c * 8], kg + r * HDn + c * 8);
            cp_async16(&vsb[r * KSs + c * 8], vg + r * HDn + c * 8);
        }
        if (t < 16) cp_async16(&kbt_base[st * 64 + t * 4],
                               kbias + (size_t)bh * Nn + kt * 64 + t * 4);
    };

    prefetch(0, 0); cp_commit();
    prefetch(1, 1); cp_commit();

    uint32_t qa[12][4];
    {
        const __half* qb = Qg + ((size_t)bh * Nn + qt * 128) * HDn;
#pragma unroll
        for (int k16 = 0; k16 < 12; k16++) {
            const int kk = k16 * 16;
            qa[k16][0] = *(const uint32_t*)&qb[(r0 + lr4)     * HDn + kk + 2 * lc4];
            qa[k16][1] = *(const uint32_t*)&qb[(r0 + lr4 + 8) * HDn + kk + 2 * lc4];
            qa[k16][2] = *(const uint32_t*)&qb[(r0 + lr4)     * HDn + kk + 8 + 2 * lc4];
            qa[k16][3] = *(const uint32_t*)&qb[(r0 + lr4 + 8) * HDn + kk + 8 + 2 * lc4];
        }
    }

    float O[24][4];
#pragma unroll
    for (int nt = 0; nt < 24; nt++)
#pragma unroll
        for (int q = 0; q < 4; q++) O[nt][q] = 0.f;
    float mr0 = -1e30f, mr1 = -1e30f, l0 = 0.f, l1 = 0.f;

    for (int kp = 0; kp < Nn / 128; kp++) {
        cp_wait<0>();       // pair kp fully resident
        __syncthreads();
        if (kp + 1 < Nn / 128) {
            prefetch(2 * kp + 2, (2 * kp + 2) & 3); cp_commit();
            prefetch(2 * kp + 3, (2 * kp + 3) & 3); cp_commit();
        }

        const int stA = (2 * kp) & 3, stB = (2 * kp + 1) & 3;
        const uint32_t ksA = (uint32_t)__cvta_generic_to_shared(ks_base + stA * KVST);
        const uint32_t ksB = (uint32_t)__cvta_generic_to_shared(ks_base + stB * KVST);
        const uint32_t vsA = (uint32_t)__cvta_generic_to_shared(vs_base + stA * KVST);
        const uint32_t vsB = (uint32_t)__cvta_generic_to_shared(vs_base + stB * KVST);
        const float* kbtA = kbt_base + stA * 64;
        const float* kbtB = kbt_base + stB * 64;

        // ---- S over 128 keys: s0 (stage A), s1 (stage B) ----
        float s0[8][4], s1[8][4];
#pragma unroll
        for (int nt = 0; nt < 8; nt++)
#pragma unroll
            for (int q = 0; q < 4; q++) { s0[nt][q] = 0.f; s1[nt][q] = 0.f; }
#pragma unroll
        for (int k16 = 0; k16 < 12; k16++) {
            const int kk = k16 * 16;
            uint32_t bf[8][2];
#pragma unroll
            for (int p = 0; p < 4; p++) {
                const int row = p * 16 + (g8 >> 1) * 8 + l8;
                const int col = kk + (g8 & 1) * 8;
                ldsm4(bf[2 * p][0], bf[2 * p][1], bf[2 * p + 1][0], bf[2 * p + 1][1],
                      ksA + (row * KSs + col) * 2);
            }
#pragma unroll
            for (int nt = 0; nt < 8; nt++)
                mma16h(s0[nt], qa[k16][0], qa[k16][1], qa[k16][2], qa[k16][3],
                       bf[nt][0], bf[nt][1]);
        }
#pragma unroll
        for (int k16 = 0; k16 < 12; k16++) {
            const int kk = k16 * 16;
            uint32_t bf[8][2];
#pragma unroll
            for (int p = 0; p < 4; p++) {
                const int row = p * 16 + (g8 >> 1) * 8 + l8;
                const int col = kk + (g8 & 1) * 8;
                ldsm4(bf[2 * p][0], bf[2 * p][1], bf[2 * p + 1][0], bf[2 * p + 1][1],
                      ksB + (row * KSs + col) * 2);
            }
#pragma unroll
            for (int nt = 0; nt < 8; nt++)
                mma16h(s1[nt], qa[k16][0], qa[k16][1], qa[k16][2], qa[k16][3],
                       bf[nt][0], bf[nt][1]);
        }

        // ---- joint bias + rowmax over 128 keys ----
        float pm0 = -1e30f, pm1 = -1e30f;
#pragma unroll
        for (int nt = 0; nt < 8; nt++) {
            const int col = nt * 8 + 2 * lc4;
            const float a0 = kbtA[col], a1 = kbtA[col + 1];
            const float b0 = kbtB[col], b1 = kbtB[col + 1];
            s0[nt][0] += a0; s0[nt][1] += a1;
            s0[nt][2] += a0; s0[nt][3] += a1;
            s1[nt][0] += b0; s1[nt][1] += b1;
            s1[nt][2] += b0; s1[nt][3] += b1;
            pm0 = fmaxf(pm0, fmaxf(fmaxf(s0[nt][0], s0[nt][1]), fmaxf(s1[nt][0], s1[nt][1])));
            pm1 = fmaxf(pm1, fmaxf(fmaxf(s0[nt][2], s0[nt][3]), fmaxf(s1[nt][2], s1[nt][3])));
        }
        pm0 = fmaxf(pm0, __shfl_xor_sync(0xffffffffu, pm0, 1));
        pm0 = fmaxf(pm0, __shfl_xor_sync(0xffffffffu, pm0, 2));
        pm1 = fmaxf(pm1, __shfl_xor_sync(0xffffffffu, pm1, 1));
        pm1 = fmaxf(pm1, __shfl_xor_sync(0xffffffffu, pm1, 2));
        const float mn0 = fmaxf(mr0, pm0), mn1 = fmaxf(mr1, pm1);
        const float cor0 = __expf(mr0 - mn0), cor1 = __expf(mr1 - mn1);
        mr0 = mn0; mr1 = mn1;

        // ---- exp both halves -> pa0/pa1; joint rowsum ----
        uint32_t pa0[4][4], pa1[4][4];
        float q0 = 0.f, q1 = 0.f;
#pragma unroll
        for (int j = 0; j < 4; j++) {
#pragma unroll
            for (int hh = 0; hh < 2; hh++) {
                const int nt = 2 * j + hh;
                {
                    const float e0 = __expf(s0[nt][0] - mn0);
                    const float e1 = __expf(s0[nt][1] - mn0);
                    const float e2 = __expf(s0[nt][2] - mn1);
                    const float e3 = __expf(s0[nt][3] - mn1);
                    q0 += e0 + e1; q1 += e2 + e3;
                    pa0[j][2 * hh]     = h2u(__floats2half2_rn(e0, e1));
                    pa0[j][2 * hh + 1] = h2u(__floats2half2_rn(e2, e3));
                }
                {
                    const float e0 = __expf(s1[nt][0] - mn0);
                    const float e1 = __expf(s1[nt][1] - mn0);
                    const float e2 = __expf(s1[nt][2] - mn1);
                    const float e3 = __expf(s1[nt][3] - mn1);
                    q0 += e0 + e1; q1 += e2 + e3;
                    pa1[j][2 * hh]     = h2u(__floats2half2_rn(e0, e1));
                    pa1[j][2 * hh + 1] = h2u(__floats2half2_rn(e2, e3));
                }
            }
        }
        q0 += __shfl_xor_sync(0xffffffffu, q0, 1);
        q0 += __shfl_xor_sync(0xffffffffu, q0, 2);
        q1 += __shfl_xor_sync(0xffffffffu, q1, 1);
        q1 += __shfl_xor_sync(0xffffffffu, q1, 2);
        l0 = l0 * cor0 + q0;
        l1 = l1 * cor1 + q1;
#pragma unroll
        for (int nt = 0; nt < 24; nt++) {
            O[nt][0] *= cor0; O[nt][1] *= cor0;
            O[nt][2] *= cor1; O[nt][3] *= cor1;
        }

        // ---- O += P @ V for both stages ----
#pragma unroll
        for (int j = 0; j < 4; j++) {
            const int kk = j * 16;
#pragma unroll
            for (int p = 0; p < 12; p++) {
                const int rowv = kk + (g8 & 1) * 8 + l8;
                const int colv = p * 16 + (g8 >> 1) * 8;
                uint32_t b0A, b1A, b0B, b1B;
                ldsm4t(b0A, b1A, b0B, b1B, vsA + (rowv * KSs + colv) * 2);
                mma16h(O[2 * p],     pa0[j][0], pa0[j][1], pa0[j][2], pa0[j][3], b0A, b1A);
                mma16h(O[2 * p + 1], pa0[j][0], pa0[j][1], pa0[j][2], pa0[j][3], b0B, b1B);
            }
        }
#pragma unroll
        for (int j = 0; j < 4; j++) {
            const int kk = j * 16;
#pragma unroll
            for (int p = 0; p < 12; p++) {
                const int rowv = kk + (g8 & 1) * 8 + l8;
                const int colv = p * 16 + (g8 >> 1) * 8;
                uint32_t b0A, b1A, b0B, b1B;
                ldsm4t(b0A, b1A, b0B, b1B, vsB + (rowv * KSs + colv) * 2);
                mma16h(O[2 * p],     pa1[j][0], pa1[j][1], pa1[j][2], pa1[j][3], b0A, b1A);
                mma16h(O[2 * p + 1], pa1[j][0], pa1[j][1], pa1[j][2], pa1[j][3], b0B, b1B);
            }
        }
    }

    const float i0v = 1.0f / l0, i1v = 1.0f / l1;
    const int nrow0 = qt * 128 + r0 + lr4;
    __half* y0 = y + (size_t)(b * Nn + nrow0) * Cdim + h * HDn;
    __half* y1 = y0 + 8 * Cdim;
#pragma unroll
    for (int nt = 0; nt < 24; nt++) {
        const int col = nt * 8 + 2 * lc4;
        *(__half2*)&y0[col] = __floats2half2_rn(O[nt][0] * i0v, O[nt][1] * i0v);
        *(__half2*)&y1[col] = __floats2half2_rn(O[nt][2] * i1v, O[nt][3] * i1v);
    }
}

// ---------------- fused LN2 + RBF + fc + residual -> out (2 rows / warp-iter) --------
constexpr int RBF_SMEM_BYTES = (2 * CEN * Cdim + 2 * CEN) * 4;  // 123040 B

__global__ __launch_bounds__(256) void rbf_final_kernel(
    const float* __restrict__ x1, const float* __restrict__ n2w,
    const float* __restrict__ n2b, const float* __restrict__ centers,
    const float* __restrict__ beta, const float* __restrict__ fcw,
    float* __restrict__ out)
{
    extern __shared__ __align__(16) float rsm[];
    float* cs   = rsm;                       // [CEN][Cdim] centers
    float* fwT  = rsm + CEN * Cdim;          // [CEN][Cdim] fc_w transposed
    float* cn   = fwT + CEN * Cdim;          // [CEN]
    float* bt   = cn + CEN;                  // [CEN]
    const int t = threadIdx.x;
    for (int i = t; i < CEN * Cdim; i += 256) {
        cs[i] = centers[i];
        const int j = i / Cdim, c = i % Cdim;
        fwT[i] = fcw[c * CEN + j];
    }
    __syncthreads();
    if (t < CEN) {
        float s = 0.f;
        for (int k = 0; k < Cdim; k++) s += cs[t * Cdim + k] * cs[t * Cdim + k];
        cn[t] = s;
        bt[t] = beta[t];
    }
    __syncthreads();
    const int wid = t >> 5, lane = t & 31;
    const float4* w4 = (const float4*)n2w;
    const float4* b4 = (const float4*)n2b;

    for (int rr = 0; rr < 4; rr++) {
        const int row0 = blockIdx.x * 64 + wid * 8 + rr * 2;
        const float4* xr0 = (const float4*)(x1 + (size_t)row0 * Cdim);
        const float4* xr1 = (const float4*)(x1 + (size_t)(row0 + 1) * Cdim);

        float hv0[24], hv1[24];
        float a0, a1;
        {   // row0 LN
            float4 v[6];
            float s = 0.f, s2 = 0.f;
#pragma unroll
            for (int i = 0; i < 6; i++) {
                v[i] = xr0[lane + i * 32];
                s  += v[i].x + v[i].y + v[i].z + v[i].w;
                s2 += v[i].x * v[i].x + v[i].y * v[i].y + v[i].z * v[i].z + v[i].w * v[i].w;
            }
            s = warpsum32(s); s2 = warpsum32(s2);
            const float mu = s * (1.0f / Cdim);
            const float rs = rsqrtf(s2 * (1.0f / Cdim) - mu * mu + EPSv);
            float a = 0.f;
#pragma unroll
            for (int i = 0; i < 6; i++) {
                const int idx = lane + i * 32;
                const float4 wv = w4[idx], bv = b4[idx];
                hv0[4*i+0] = (v[i].x - mu) * rs * wv.x + bv.x;
                hv0[4*i+1] = (v[i].y - mu) * rs * wv.y + bv.y;
                hv0[4*i+2] = (v[i].z - mu) * rs * wv.z + bv.z;
                hv0[4*i+3] = (v[i].w - mu) * rs * wv.w + bv.w;
                a += hv0[4*i]*hv0[4*i] + hv0[4*i+1]*hv0[4*i+1]
                   + hv0[4*i+2]*hv0[4*i+2] + hv0[4*i+3]*hv0[4*i+3];
            }
            a0 = warpsum32(a);
        }
        {   // row1 LN
            float4 v[6];
            float s = 0.f, s2 = 0.f;
#pragma unroll
            for (int i = 0; i < 6; i++) {
                v[i] = xr1[lane + i * 32];
                s  += v[i].x + v[i].y + v[i].z + v[i].w;
                s2 += v[i].x * v[i].x + v[i].y * v[i].y + v[i].z * v[i].z + v[i].w * v[i].w;
            }
            s = warpsum32(s); s2 = warpsum32(s2);
            const float mu = s * (1.0f / Cdim);
            const float rs = rsqrtf(s2 * (1.0f / Cdim) - mu * mu + EPSv);
            float a = 0.f;
#pragma unroll
            for (int i = 0; i < 6; i++) {
                const int idx = lane + i * 32;
                const float4 wv = w4[idx], bv = b4[idx];
                hv1[4*i+0] = (v[i].x - mu) * rs * wv.x + bv.x;
                hv1[4*i+1] = (v[i].y - mu) * rs * wv.y + bv.y;
                hv1[4*i+2] = (v[i].z - mu) * rs * wv.z + bv.z;
                hv1[4*i+3] = (v[i].w - mu) * rs * wv.w + bv.w;
                a += hv1[4*i]*hv1[4*i] + hv1[4*i+1]*hv1[4*i+1]
                   + hv1[4*i+2]*hv1[4*i+2] + hv1[4*i+3]*hv1[4*i+3];
            }
            a1 = warpsum32(a);
        }

        float rj0[CEN], rj1[CEN];
#pragma unroll
        for (int j = 0; j < CEN; j++) {
            const float4* cj = (const float4*)(cs + j * Cdim);
            float d0 = 0.f, d1 = 0.f;
#pragma unroll
            for (int i = 0; i < 6; i++) {
                const float4 cv = cj[lane + i * 32];
                d0 += hv0[4*i]*cv.x + hv0[4*i+1]*cv.y + hv0[4*i+2]*cv.z + hv0[4*i+3]*cv.w;
                d1 += hv1[4*i]*cv.x + hv1[4*i+1]*cv.y + hv1[4*i+2]*cv.z + hv1[4*i+3]*cv.w;
            }
            d0 = warpsum32(d0); d1 = warpsum32(d1);
            rj0[j] = __expf(-bt[j] * (a0 - 2.0f * d0 + cn[j]));
            rj1[j] = __expf(-bt[j] * (a1 - 2.0f * d1 + cn[j]));
        }

        float4* o0row = (float4*)(out + (size_t)row0 * Cdim);
        float4* o1row = (float4*)(out + (size_t)(row0 + 1) * Cdim);
#pragma unroll
        for (int i = 0; i < 6; i++) {
            const int idx = lane + i * 32;
            float4 o0 = xr0[idx];
            float4 o1 = xr1[idx];
#pragma unroll
            for (int j = 0; j < CEN; j++) {
                const float4 fv = *(const float4*)&fwT[j * Cdim + 4 * idx];
                o0.x += rj0[j] * fv.x; o0.y += rj0[j] * fv.y;
                o0.z += rj0[j] * fv.z; o0.w += rj0[j] * fv.w;
                o1.x += rj1[j] * fv.x; o1.y += rj1[j] * fv.y;
                o1.z += rj1[j] * fv.z; o1.w += rj1[j] * fv.w;
            }
            o0row[idx] = o0;
            o1row[idx] = o1;
        }
    }
}

// ---------------- launcher ----------------
extern "C" void kernel_launch(void* const* d_in, const int* in_sizes, int n_in,
                              void* d_out, int out_size)
{
    (void)in_sizes; (void)n_in; (void)out_size;
    const float* x     = (const float*)d_in[0];
    const float* n1w   = (const float*)d_in[1];
    const float* n1b   = (const float*)d_in[2];
    const float* qkvw  = (const float*)d_in[3];
    const float* Mmat  = (const float*)d_in[4];
    const float* scale = (const float*)d_in[5];
    const float* projw = (const float*)d_in[6];
    const float* projb = (const float*)d_in[7];
    const float* n2w   = (const float*)d_in[8];
    const float* n2b   = (const float*)d_in[9];
    const float* cent  = (const float*)d_in[10];
    const float* beta  = (const float*)d_in[11];
    const float* fcw   = (const float*)d_in[12];
    float* out = (float*)d_out;

    __half *hP, *qwP, *pwP, *QgP, *KgP, *VgP, *KMP, *MhP, *yP;
    float *kbpP, *kbP, *x1P;
    cudaGetSymbolAddress((void**)&hP,   g_h);
    cudaGetSymbolAddress((void**)&qwP,  g_qkvwr);
    cudaGetSymbolAddress((void**)&pwP,  g_projwr);
    cudaGetSymbolAddress((void**)&QgP,  g_Qg);
    cudaGetSymbolAddress((void**)&KgP,  g_Kg);
    cudaGetSymbolAddress((void**)&VgP,  g_Vg);
    cudaGetSymbolAddress((void**)&KMP,  g_KM);
    cudaGetSymbolAddress((void**)&MhP,  g_Mh);
    cudaGetSymbolAddress((void**)&kbpP, g_kbp);
    cudaGetSymbolAddress((void**)&kbP,  g_kb);
    cudaGetSymbolAddress((void**)&yP,   g_y);
    cudaGetSymbolAddress((void**)&x1P,  g_x1);

    constexpr int GS128 = 3 * (128 + 128) * 64 * 2;   // 98304 B
    constexpr int GS64  = 3 * (128 + 64) * 64 * 2;    // 73728 B
    cudaFuncSetAttribute(gemm_h<128, 1>, cudaFuncAttributeMaxDynamicSharedMemorySize, GS128);
    cudaFuncSetAttribute(gemm_h<128, 2>, cudaFuncAttributeMaxDynamicSharedMemorySize, GS128);
    cudaFuncSetAttribute(gemm_h<64, 3>,  cudaFuncAttributeMaxDynamicSharedMemorySize, GS64);
    cudaFuncSetAttribute(attn_tc_kernel, cudaFuncAttributeMaxDynamicSharedMemorySize, ATT_SMEM);
    cudaFuncSetAttribute(rbf_final_kernel, cudaFuncAttributeMaxDynamicSharedMemorySize, RBF_SMEM_BYTES);

    // streams/events for prep overlap (created once; reused across calls)
    static cudaStream_t sA = nullptr, sB = nullptr;
    static cudaEvent_t  eF = nullptr, eA = nullptr, eB = nullptr;
    if (!sA) {
        cudaStreamCreateWithFlags(&sA, cudaStreamNonBlocking);
        cudaStreamCreateWithFlags(&sB, cudaStreamNonBlocking);
        cudaEventCreateWithFlags(&eF, cudaEventDisableTiming);
        cudaEventCreateWithFlags(&eA, cudaEventDisableTiming);
        cudaEventCreateWithFlags(&eB, cudaEventDisableTiming);
    }

    // fork prep work onto side streams
    cudaEventRecord(eF, 0);
    cudaStreamWaitEvent(sA, eF, 0);
    cudaStreamWaitEvent(sB, eF, 0);
    half_copy4_kernel<<<512, 256, 0, sA>>>((const float4*)qkvw, qwP, 3 * Cdim * Cdim / 4);
    cudaEventRecord(eA, sA);
    half_copy4_kernel<<<256, 256, 0, sB>>>((const float4*)projw, pwP, Cdim * Cdim / 4);
    scale_m_kernel<<<(HDn * HDn + 255) / 256, 256, 0, sB>>>(Mmat, scale, MhP);
    cudaEventRecord(eB, sB);

    // 1) LN1 (half out) — overlaps the weight conversions
    ln1_kernel<<<Sn / 8, 256>>>(x, n1w, n1b, hP);
    // join qkv weights
    cudaStreamWaitEvent(0, eA, 0);
    // 2) qkv GEMM fused with gather -> Qg/Kg/Vg (half)
    gemm_h<128, 1><<<dim3(3 * Cdim / 128, Sn / 128), 256, GS128>>>(
        hP, qwP, QgP, KgP, VgP, Sn, 3 * Cdim, Cdim, nullptr, nullptr, nullptr);
    // join Mh (+proj weights, conservative)
    cudaStreamWaitEvent(0, eB, 0);
    // 3) KM2 = K @ (2*scale*M)^T with fused kbias partials
    gemm_h<64, 3><<<dim3(HDn / 64, BHn * Nn / 128), 256, GS64>>>(
        KgP, MhP, KMP, nullptr, nullptr, BHn * Nn, HDn, HDn, nullptr, nullptr, kbpP);
    // 4) kb = -0.5 * sum(partials)
    kb_reduce_kernel<<<(BHn * Nn + 255) / 256, 256>>>(kbpP, kbP);
    // 5) fp16 flash attention (128-key softmax cadence) -> y (half)
    attn_tc_kernel<<<dim3(BHn, Nn / 128), 256, ATT_SMEM>>>(QgP, KMP, VgP, kbP, yP);
    // 6) x1 = x + y @ proj_w^T + proj_b (fp32 out)
    gemm_h<128, 2><<<dim3(Cdim / 128, Sn / 128), 256, GS128>>>(
        yP, pwP, x1P, nullptr, nullptr, Sn, Cdim, Cdim, projb, x, nullptr);
    // 7) fused LN2 + RBF + fc + residual -> out
    rbf_final_kernel<<<Sn / 64, 256, RBF_SMEM_BYTES>>>(x1P, n2w, n2b, cent, beta, fcw, out);
}